// round 13
// baseline (speedup 1.0000x reference)
#include <cuda_runtime.h>
#include <cuda_fp16.h>
#include <math.h>
#include <cstdint>

// Problem constants
#define BATCH 2
#define SEQ   2048
#define EMB   2048
#define HEADS 16
#define DHEAD 128
#define DROPE 32
#define SPLIT 96
#define CLAT  512
#define NTOK  (BATCH*SEQ)          // 4096
#define HD    (HEADS*DHEAD)        // 2048

// ---------------------------------------------------------------------------
// Global scratch (fp16 planes)
// ---------------------------------------------------------------------------
constexpr size_t OF_HH   = 0;
constexpr size_t OF_HL   = OF_HH   + (size_t)NTOK*EMB;
constexpr size_t OF_DKVH = OF_HL   + (size_t)NTOK*EMB;
constexpr size_t OF_DKVL = OF_DKVH + (size_t)EMB*CLAT;
constexpr size_t OF_DQH  = OF_DKVL + (size_t)EMB*CLAT;
constexpr size_t OF_DQL  = OF_DQH  + (size_t)EMB*CLAT;
constexpr size_t OF_KRH  = OF_DQL  + (size_t)EMB*CLAT;
constexpr size_t OF_KRL  = OF_KRH  + (size_t)EMB*(HEADS*DROPE);
constexpr size_t OF_UKH  = OF_KRL  + (size_t)EMB*(HEADS*DROPE);
constexpr size_t OF_UKL  = OF_UKH  + (size_t)CLAT*(HEADS*SPLIT);
constexpr size_t OF_UVH  = OF_UKL  + (size_t)CLAT*(HEADS*SPLIT);
constexpr size_t OF_UQH  = OF_UVH  + (size_t)CLAT*HD;
constexpr size_t OF_UQL  = OF_UQH  + (size_t)CLAT*(HEADS*SPLIT);
constexpr size_t OF_QRH  = OF_UQL  + (size_t)CLAT*(HEADS*SPLIT);
constexpr size_t OF_QRL  = OF_QRH  + (size_t)CLAT*(HEADS*DROPE);
constexpr size_t OF_OUTH = OF_QRL  + (size_t)CLAT*(HEADS*DROPE);
constexpr size_t OF_CKVH = OF_OUTH + (size_t)HD*EMB;
constexpr size_t OF_CKVL = OF_CKVH + (size_t)NTOK*CLAT;
constexpr size_t OF_CQH  = OF_CKVL + (size_t)NTOK*CLAT;
constexpr size_t OF_CQL  = OF_CQH  + (size_t)NTOK*CLAT;
constexpr size_t OF_QH   = OF_CQL  + (size_t)NTOK*CLAT;
constexpr size_t OF_QL   = OF_QH   + (size_t)NTOK*HD;
constexpr size_t OF_KH   = OF_QL   + (size_t)NTOK*HD;
constexpr size_t OF_KL   = OF_KH   + (size_t)NTOK*HD;
constexpr size_t OF_VH   = OF_KL   + (size_t)NTOK*HD;
constexpr size_t OF_AOH  = OF_VH   + (size_t)NTOK*HD;
constexpr size_t OF_AOL  = OF_AOH  + (size_t)NTOK*HD;
constexpr size_t BF_TOTAL= OF_AOL  + (size_t)NTOK*HD;

__device__ __half g_bf[BF_TOTAL];
__device__ float g_qr[NTOK * HEADS * DROPE];
__device__ float g_kr[NTOK * HEADS * DROPE];

// ---------------------------------------------------------------------------
// Helpers
// ---------------------------------------------------------------------------
__device__ __forceinline__ uint32_t smem_u32(const void* p) {
    uint32_t a;
    asm("{ .reg .u64 t; cvta.to.shared.u64 t, %1; cvt.u32.u64 %0, t; }"
        : "=r"(a) : "l"(p));
    return a;
}
__device__ __forceinline__ uint32_t packhf(float e0, float e1) {
    uint32_t r;
    asm("cvt.rn.f16x2.f32 %0, %1, %2;" : "=r"(r) : "f"(e1), "f"(e0));
    return r;
}
__device__ __forceinline__ float hrt(float x) {
    return __half2float(__float2half_rn(x));
}
__device__ __forceinline__ void ldsm_x4(uint32_t& r0, uint32_t& r1, uint32_t& r2,
                                        uint32_t& r3, uint32_t addr) {
    asm volatile("ldmatrix.sync.aligned.m8n8.x4.shared.b16 {%0,%1,%2,%3}, [%4];"
                 : "=r"(r0), "=r"(r1), "=r"(r2), "=r"(r3) : "r"(addr));
}
__device__ __forceinline__ void ldsm_x4t(uint32_t& r0, uint32_t& r1, uint32_t& r2,
                                         uint32_t& r3, uint32_t addr) {
    asm volatile("ldmatrix.sync.aligned.m8n8.x4.trans.shared.b16 {%0,%1,%2,%3}, [%4];"
                 : "=r"(r0), "=r"(r1), "=r"(r2), "=r"(r3) : "r"(addr));
}
__device__ __forceinline__ void mma_f16(float* d, const uint32_t* a, const uint32_t* b) {
    asm volatile(
        "mma.sync.aligned.m16n8k16.row.col.f32.f16.f16.f32 "
        "{%0,%1,%2,%3}, {%4,%5,%6,%7}, {%8,%9}, {%0,%1,%2,%3};"
        : "+f"(d[0]), "+f"(d[1]), "+f"(d[2]), "+f"(d[3])
        : "r"(a[0]), "r"(a[1]), "r"(a[2]), "r"(a[3]), "r"(b[0]), "r"(b[1]));
}
__device__ __forceinline__ void cp16(uint32_t saddr, const void* gaddr) {
    asm volatile("cp.async.cg.shared.global [%0], [%1], 16;" :: "r"(saddr), "l"(gaddr));
}
__device__ __forceinline__ void cp_commit() {
    asm volatile("cp.async.commit_group;" ::: "memory");
}
template<int N> __device__ __forceinline__ void cp_wait() {
    asm volatile("cp.async.wait_group %0;" :: "n"(N) : "memory");
}

// ---------------------------------------------------------------------------
// Batched fp32 -> fp16 hi/lo split kernel (lo optional)
// ---------------------------------------------------------------------------
struct SDesc { const float* src; uint32_t* hi; uint32_t* lo; int end4; };
struct SBatch { SDesc d[9]; int total4; };

__global__ void split_all_kernel(SBatch sb)
{
    int i = blockIdx.x * blockDim.x + threadIdx.x;
    if (i >= sb.total4) return;
    int g = 0;
    while (i >= sb.d[g].end4) g++;
    int start = (g == 0) ? 0 : sb.d[g-1].end4;
    int li = i - start;
    float4 v = ((const float4*)sb.d[g].src)[li];
    float h0 = hrt(v.x), h1 = hrt(v.y), h2 = hrt(v.z), h3 = hrt(v.w);
    sb.d[g].hi[li*2]   = packhf(h0, h1);
    sb.d[g].hi[li*2+1] = packhf(h2, h3);
    if (sb.d[g].lo) {
        sb.d[g].lo[li*2]   = packhf(v.x - h0, v.y - h1);
        sb.d[g].lo[li*2+1] = packhf(v.z - h2, v.w - h3);
    }
}

// ---------------------------------------------------------------------------
// Persistent multi-GEMM: CTA 128x128, 128 threads, warp 64x64, BK=32,
// double-buffered cp.async, 2 CTAs/SM, 3- or 2-term fp16.
// ---------------------------------------------------------------------------
#define BM 128
#define BN 128
#define BK 32
#define PA 40
#define PB 136
#define A_PLANE (BM*PA*2)
#define B_PLANE (BK*PB*2)
#define OFF_AHI 0
#define OFF_ALO (A_PLANE)
#define OFF_BHI (2*A_PLANE)
#define OFF_BLO (2*A_PLANE + B_PLANE)
#define SBUF    (2*A_PLANE + 2*B_PLANE)
#define GSMEM   (2*SBUF)

struct GDesc {
    const __half *Ah, *Al, *Bh, *Bl;
    const float* bias;
    float* Cf;
    __half *Ch, *Cl;
    int N, K, seg, hstride, col_off, ostride;
    float scale;
    int two_term;
    int tile_end;
};
struct GBatch { GDesc d[4]; int total; };

__device__ __forceinline__ void gemm_issue(
    const __half* Ah, const __half* Al,
    const __half* Bh, const __half* Bl, int two_term,
    int m0, int n0, int kk, int K, int N, uint32_t base, int t)
{
#pragma unroll
    for (int i = 0; i < 4; i++) {
        int f = t + i * 128;
        int m = f >> 2, g = f & 3;
        size_t gi = (size_t)(m0 + m) * K + kk + g * 8;
        uint32_t so = (uint32_t)(m * (PA*2) + g * 16);
        cp16(base + OFF_AHI + so, Ah + gi);
        cp16(base + OFF_ALO + so, Al + gi);
    }
#pragma unroll
    for (int i = 0; i < 4; i++) {
        int f = t + i * 128;
        int k2 = f >> 4, nc = f & 15;
        size_t gi = (size_t)(kk + k2) * N + n0 + nc * 8;
        uint32_t so = (uint32_t)(k2 * (PB*2) + nc * 16);
        cp16(base + OFF_BHI + so, Bh + gi);
        if (!two_term) cp16(base + OFF_BLO + so, Bl + gi);
    }
}

__global__ __launch_bounds__(128, 2)
void bf_gemm_ws(GBatch batch)
{
    extern __shared__ char smc[];
    const uint32_t sb = smem_u32(smc);
    const int t    = threadIdx.x;
    const int lane = t & 31;
    const int w    = t >> 5;
    const int wm   = (w >> 1) * 64;
    const int wn   = (w & 1) * 64;

    const uint32_t aLane = (uint32_t)((wm + (lane & 15)) * PA + (lane >> 4) * 8) * 2;
    const uint32_t bLaneRow = (uint32_t)(lane & 15) * (PB * 2);
    const uint32_t bLaneCol = (uint32_t)(wn + (lane >> 4) * 8) * 2;

    for (int tile = blockIdx.x; tile < batch.total; tile += gridDim.x) {
        int g = 0;
        while (tile >= batch.d[g].tile_end) g++;
        const GDesc& d = batch.d[g];
        const int tbase = (g == 0) ? 0 : batch.d[g-1].tile_end;
        const int lt  = tile - tbase;
        const int ntn = d.N / BN;
        const int m0  = (lt / ntn) * BM;
        const int n0  = (lt % ntn) * BN;
        const int NC  = d.K / BK;
        const int twot = d.two_term;

        float acc[4][8][4];
#pragma unroll
        for (int i = 0; i < 4; i++)
#pragma unroll
            for (int j = 0; j < 8; j++)
#pragma unroll
                for (int r = 0; r < 4; r++) acc[i][j][r] = 0.f;

        gemm_issue(d.Ah, d.Al, d.Bh, d.Bl, twot, m0, n0, 0, d.K, d.N, sb, t);
        cp_commit();

        for (int ch = 0; ch < NC; ch++) {
            if (ch + 1 < NC) {
                gemm_issue(d.Ah, d.Al, d.Bh, d.Bl, twot, m0, n0, (ch + 1) * BK, d.K, d.N,
                           sb + (uint32_t)((ch + 1) & 1) * SBUF, t);
                cp_commit();
                cp_wait<1>();
            } else {
                cp_wait<0>();
            }
            __syncthreads();

            const uint32_t base = sb + (uint32_t)(ch & 1) * SBUF;
#pragma unroll
            for (int ks = 0; ks < 2; ks++) {
                uint32_t Fah[4][4], Fal[4][4];
                const uint32_t aOff = aLane + (uint32_t)ks * 32;
#pragma unroll
                for (int mt = 0; mt < 4; mt++) {
                    uint32_t ad = base + aOff + (uint32_t)mt * (16 * PA * 2);
                    ldsm_x4(Fah[mt][0], Fah[mt][1], Fah[mt][2], Fah[mt][3], ad + OFF_AHI);
                    ldsm_x4(Fal[mt][0], Fal[mt][1], Fal[mt][2], Fal[mt][3], ad + OFF_ALO);
                }
                const uint32_t bOff = bLaneRow + (uint32_t)ks * (16 * PB * 2) + bLaneCol;
                if (twot) {
#pragma unroll
                    for (int np = 0; np < 4; np++) {
                        uint32_t Bh[4];
                        uint32_t bd = base + bOff + (uint32_t)np * 32;
                        ldsm_x4t(Bh[0], Bh[1], Bh[2], Bh[3], bd + OFF_BHI);
#pragma unroll
                        for (int mt = 0; mt < 4; mt++) {
                            mma_f16(acc[mt][2*np],   Fah[mt], &Bh[0]);
                            mma_f16(acc[mt][2*np],   Fal[mt], &Bh[0]);
                            mma_f16(acc[mt][2*np+1], Fah[mt], &Bh[2]);
                            mma_f16(acc[mt][2*np+1], Fal[mt], &Bh[2]);
                        }
                    }
                } else {
#pragma unroll
                    for (int np = 0; np < 4; np++) {
                        uint32_t Bh[4], Bl[4];
                        uint32_t bd = base + bOff + (uint32_t)np * 32;
                        ldsm_x4t(Bh[0], Bh[1], Bh[2], Bh[3], bd + OFF_BHI);
                        ldsm_x4t(Bl[0], Bl[1], Bl[2], Bl[3], bd + OFF_BLO);
#pragma unroll
                        for (int mt = 0; mt < 4; mt++) {
                            mma_f16(acc[mt][2*np],   Fah[mt], &Bh[0]);
                            mma_f16(acc[mt][2*np],   Fah[mt], &Bl[0]);
                            mma_f16(acc[mt][2*np],   Fal[mt], &Bh[0]);
                            mma_f16(acc[mt][2*np+1], Fah[mt], &Bh[2]);
                            mma_f16(acc[mt][2*np+1], Fah[mt], &Bl[2]);
                            mma_f16(acc[mt][2*np+1], Fal[mt], &Bh[2]);
                        }
                    }
                }
            }
            __syncthreads();
        }

        const int r0 = lane >> 2;
        const int c0 = (lane & 3) * 2;
#pragma unroll
        for (int mt = 0; mt < 4; mt++) {
#pragma unroll
            for (int nt = 0; nt < 8; nt++) {
                int n = n0 + wn + nt * 8 + c0;
                int oc = (n / d.seg) * d.hstride + (n % d.seg) + d.col_off;
                float b0 = d.bias[n], b1 = d.bias[n + 1];
                int mrow0 = m0 + wm + mt * 16 + r0;
#pragma unroll
                for (int half = 0; half < 2; half++) {
                    size_t row = (size_t)(mrow0 + half * 8);
                    float v0 = (acc[mt][nt][half*2]   + b0) * d.scale;
                    float v1 = (acc[mt][nt][half*2+1] + b1) * d.scale;
                    if (d.Cf) *(float2*)&d.Cf[row * d.ostride + oc] = make_float2(v0, v1);
                    if (d.Ch) {
                        float h0 = hrt(v0), h1 = hrt(v1);
                        *(uint32_t*)&d.Ch[row * d.ostride + oc] = packhf(h0, h1);
                        if (d.Cl)
                            *(uint32_t*)&d.Cl[row * d.ostride + oc] = packhf(v0 - h0, v1 - h1);
                    }
                }
            }
        }
    }
}

// ---------------------------------------------------------------------------
// Rotary: __sincosf + vectorized uint4 plane stores
// ---------------------------------------------------------------------------
__global__ void rotary_kernel(const float* __restrict__ qr,
                              const float* __restrict__ kr,
                              __half* __restrict__ qh, __half* __restrict__ ql,
                              __half* __restrict__ kh, __half* __restrict__ kl,
                              float* __restrict__ krot_out)
{
    int gid = blockIdx.x * blockDim.x + threadIdx.x;
    if (gid >= 2 * NTOK * HEADS) return;
    const bool isK = gid >= NTOK * HEADS;
    int idx = isK ? (gid - NTOK * HEADS) : gid;
    int h   = idx & (HEADS - 1);
    int tok = idx >> 4;
    int s   = tok & (SEQ - 1);
    float tpos = (float)s / 40.0f;
    const float qscale = 0.08838834764831845f;

    const float* src = isK ? kr : qr;
    float x[32];
#pragma unroll
    for (int i = 0; i < 8; i++) {
        float4 a = *(const float4*)&src[(size_t)idx * 32 + i * 4];
        x[i*4+0]=a.x; x[i*4+1]=a.y; x[i*4+2]=a.z; x[i*4+3]=a.w;
    }

    float y[32];
#pragma unroll
    for (int j = 0; j < 8; j++) {
        float invf = exp2f(-1.6609640474436813f * (float)j);
        float ang = tpos * invf;
        float sj, cj;
        __sincosf(ang, &sj, &cj);
        y[j]     = x[j] * cj - x[j + 8] * sj;
        y[j + 8] = x[j + 8] * cj + x[j] * sj;
    }
#pragma unroll
    for (int d = 16; d < 32; d++) y[d] = x[d];

    const float osc = isK ? 1.0f : qscale;
    uint32_t ph[16], pl[16];
#pragma unroll
    for (int j = 0; j < 16; j++) {
        float v0 = y[2*j] * osc, v1 = y[2*j+1] * osc;
        float h0 = hrt(v0), h1 = hrt(v1);
        ph[j] = packhf(h0, h1);
        pl[j] = packhf(v0 - h0, v1 - h1);
    }

    size_t obase = (size_t)tok * HD + h * DHEAD + SPLIT;   // 16B-aligned (96*2=192B)
    __half* dsth = isK ? kh : qh;
    __half* dstl = isK ? kl : ql;
#pragma unroll
    for (int i = 0; i < 4; i++) {
        *(uint4*)&dsth[obase + 8*i] = make_uint4(ph[4*i], ph[4*i+1], ph[4*i+2], ph[4*i+3]);
        *(uint4*)&dstl[obase + 8*i] = make_uint4(pl[4*i], pl[4*i+1], pl[4*i+2], pl[4*i+3]);
    }
    if (isK) {
#pragma unroll
        for (int i = 0; i < 8; i++)
            *(float4*)&krot_out[(size_t)idx * 32 + i * 4] =
                make_float4(y[i*4], y[i*4+1], y[i*4+2], y[i*4+3]);
    }
}

// ---------------------------------------------------------------------------
// Causal flash-attention (round-10 geometry): AM=128, 256 threads,
// double-buffered 3-plane KV (Khi,Klo,Vhi), QK 3-term, PV 2-term.
// ---------------------------------------------------------------------------
#define AM 128
#define AN 64
#define APH 136
#define AQHI 0
#define AQLO (AM*APH*2)                  // 34816
#define AKV0 (2*AM*APH*2)                // 69632
#define KVP  (AN*APH*2)                  // 17408 per plane
#define KVBUF (3*KVP)                    // 52224
#define ASMEM (AKV0 + 2*KVBUF)           // 174080

__device__ __forceinline__ void attn_issue_kv(
    const __half* kh, const __half* kl, const __half* vh,
    size_t rowbase, uint32_t kvbase, int t)
{
#pragma unroll
    for (int i = 0; i < 4; i++) {
        int f = t + i * 256;
        int row = f >> 4, ch = f & 15;
        size_t gi = (rowbase + row) * HD + ch * 8;
        uint32_t so = (uint32_t)(row * 272 + ch * 16);
        cp16(kvbase + 0*KVP + so, kh + gi);
        cp16(kvbase + 1*KVP + so, kl + gi);
        cp16(kvbase + 2*KVP + so, vh + gi);
    }
}

__global__ __launch_bounds__(256, 1)
void attn_mma_kernel(const __half* __restrict__ qh, const __half* __restrict__ ql,
                     const __half* __restrict__ kh, const __half* __restrict__ kl,
                     const __half* __restrict__ vh,
                     __half* __restrict__ aoh, __half* __restrict__ aol)
{
    extern __shared__ char smc[];
    const uint32_t sb = smem_u32(smc);
    const int t    = threadIdx.x;
    const int lane = t & 31;
    const int w    = t >> 5;
    const int bh   = blockIdx.y;
    const int b    = bh >> 4;
    const int h    = bh & 15;
    const int q0   = ((int)gridDim.x - 1 - (int)blockIdx.x) * AM;

    const size_t qrowbase = (size_t)(b * SEQ + q0);
    const __half* qhp = qh + h * DHEAD;
    const __half* qlp = ql + h * DHEAD;
    const __half* khp = kh + h * DHEAD;
    const __half* klp = kl + h * DHEAD;
    const __half* vhp = vh + h * DHEAD;

#pragma unroll
    for (int i = 0; i < 8; i++) {
        int f = t + i * 256;
        int row = f >> 4, ch = f & 15;
        size_t gi = (qrowbase + row) * HD + ch * 8;
        uint32_t so = (uint32_t)(row * 272 + ch * 16);
        cp16(sb + AQHI + so, qhp + gi);
        cp16(sb + AQLO + so, qlp + gi);
    }
    attn_issue_kv(khp, klp, vhp, (size_t)(b * SEQ), sb + AKV0, t);
    cp_commit();

    float mrow[2] = {-INFINITY, -INFINITY};
    float lrow[2] = {0.f, 0.f};
    float O[16][4];
#pragma unroll
    for (int i = 0; i < 16; i++)
#pragma unroll
        for (int r = 0; r < 4; r++) O[i][r] = 0.f;

    const int ntiles = q0 / AN + 2;
    for (int nt = 0; nt < ntiles; nt++) {
        const int n0 = nt * AN;
        if (nt + 1 < ntiles) {
            attn_issue_kv(khp, klp, vhp, (size_t)(b * SEQ + (nt + 1) * AN),
                          sb + AKV0 + (uint32_t)((nt + 1) & 1) * KVBUF, t);
            cp_commit();
            cp_wait<1>();
        } else {
            cp_wait<0>();
        }
        __syncthreads();

        const uint32_t kvb = sb + AKV0 + (uint32_t)(nt & 1) * KVBUF;
        const bool active = (q0 + w * 16 + 15) >= n0;
        if (active) {
            float S[8][4];
#pragma unroll
            for (int nf = 0; nf < 8; nf++)
#pragma unroll
                for (int r = 0; r < 4; r++) S[nf][r] = 0.f;

#pragma unroll
            for (int ks = 0; ks < 8; ks++) {
                uint32_t ah[4], al[4];
                uint32_t ad = sb + (uint32_t)((w * 16 + (lane & 15)) * APH
                                              + ks * 16 + (lane >> 4) * 8) * 2;
                ldsm_x4(ah[0], ah[1], ah[2], ah[3], ad + AQHI);
                ldsm_x4(al[0], al[1], al[2], al[3], ad + AQLO);
#pragma unroll
                for (int g = 0; g < 4; g++) {
                    uint32_t bd = kvb + (uint32_t)((g * 16 + (lane & 7) + (lane >> 4) * 8) * APH
                                                   + ks * 16 + ((lane >> 3) & 1) * 8) * 2;
                    uint32_t khf[4], klf[4];
                    ldsm_x4(khf[0], khf[1], khf[2], khf[3], bd + 0*KVP);
                    ldsm_x4(klf[0], klf[1], klf[2], klf[3], bd + 1*KVP);
                    mma_f16(S[2*g],   ah, &khf[0]);
                    mma_f16(S[2*g],   ah, &klf[0]);
                    mma_f16(S[2*g],   al, &khf[0]);
                    mma_f16(S[2*g+1], ah, &khf[2]);
                    mma_f16(S[2*g+1], ah, &klf[2]);
                    mma_f16(S[2*g+1], al, &khf[2]);
                }
            }

            if (n0 + AN - 1 > q0 + w * 16) {
                int grow0 = q0 + w * 16 + (lane >> 2);
#pragma unroll
                for (int nf = 0; nf < 8; nf++) {
                    int col = n0 + nf * 8 + (lane & 3) * 2;
#pragma unroll
                    for (int r = 0; r < 4; r++) {
                        int gr = grow0 + (r >> 1) * 8;
                        int gc = col + (r & 1);
                        if (gc > gr) S[nf][r] = -INFINITY;
                    }
                }
            }

            float corr[2];
#pragma unroll
            for (int rr = 0; rr < 2; rr++) {
                float rm = -INFINITY;
#pragma unroll
                for (int nf = 0; nf < 8; nf++)
                    rm = fmaxf(rm, fmaxf(S[nf][rr*2], S[nf][rr*2+1]));
                rm = fmaxf(rm, __shfl_xor_sync(0xffffffffu, rm, 1));
                rm = fmaxf(rm, __shfl_xor_sync(0xffffffffu, rm, 2));
                float mnew = fmaxf(mrow[rr], rm);
                corr[rr] = __expf(mrow[rr] - mnew);
                float rs = 0.f;
#pragma unroll
                for (int nf = 0; nf < 8; nf++) {
                    float p0 = __expf(S[nf][rr*2]   - mnew);
                    float p1 = __expf(S[nf][rr*2+1] - mnew);
                    S[nf][rr*2]   = p0;
                    S[nf][rr*2+1] = p1;
                    rs += p0 + p1;
                }
                rs += __shfl_xor_sync(0xffffffffu, rs, 1);
                rs += __shfl_xor_sync(0xffffffffu, rs, 2);
                lrow[rr] = lrow[rr] * corr[rr] + rs;
                mrow[rr] = mnew;
            }
#pragma unroll
            for (int i = 0; i < 16; i++) {
                O[i][0] *= corr[0]; O[i][1] *= corr[0];
                O[i][2] *= corr[1]; O[i][3] *= corr[1];
            }

#pragma unroll
            for (int j = 0; j < 4; j++) {
                uint32_t ph[4], pl[4];
                {
                    float s00 = S[2*j][0],   s01 = S[2*j][1],   s02 = S[2*j][2],   s03 = S[2*j][3];
                    float s10 = S[2*j+1][0], s11 = S[2*j+1][1], s12 = S[2*j+1][2], s13 = S[2*j+1][3];
                    float h00 = hrt(s00), h01 = hrt(s01), h02 = hrt(s02), h03 = hrt(s03);
                    float h10 = hrt(s10), h11 = hrt(s11), h12 = hrt(s12), h13 = hrt(s13);
                    ph[0] = packhf(h00, h01); ph[1] = packhf(h02, h03);
                    ph[2] = packhf(h10, h11); ph[3] = packhf(h12, h13);
                    pl[0] = packhf(s00 - h00, s01 - h01); pl[1] = packhf(s02 - h02, s03 - h03);
                    pl[2] = packhf(s10 - h10, s11 - h11); pl[3] = packhf(s12 - h12, s13 - h13);
                }
#pragma unroll
                for (int g = 0; g < 8; g++) {
                    uint32_t vd = kvb + (uint32_t)((j * 16 + (lane & 15)) * APH
                                                   + g * 16 + (lane >> 4) * 8) * 2;
                    uint32_t vhf[4];
                    ldsm_x4t(vhf[0], vhf[1], vhf[2], vhf[3], vd + 2*KVP);
                    mma_f16(O[2*g],   ph, &vhf[0]);
                    mma_f16(O[2*g],   pl, &vhf[0]);
                    mma_f16(O[2*g+1], ph, &vhf[2]);
                    mma_f16(O[2*g+1], pl, &vhf[2]);
                }
            }
        }
        __syncthreads();
    }

    float inv0 = 1.0f / lrow[0];
    float inv1 = 1.0f / lrow[1];
#pragma unroll
    for (int nd = 0; nd < 16; nd++) {
        int d = nd * 8 + (lane & 3) * 2;
        size_t row0 = (size_t)(b * SEQ + q0 + w * 16 + (lane >> 2));
        float v0 = O[nd][0] * inv0, v1 = O[nd][1] * inv0;
        float h0 = hrt(v0), h1 = hrt(v1);
        *(uint32_t*)&aoh[row0 * HD + h * DHEAD + d] = packhf(h0, h1);
        *(uint32_t*)&aol[row0 * HD + h * DHEAD + d] = packhf(v0 - h0, v1 - h1);
        float v2 = O[nd][2] * inv1, v3 = O[nd][3] * inv1;
        float h2 = hrt(v2), h3 = hrt(v3);
        *(uint32_t*)&aoh[(row0 + 8) * HD + h * DHEAD + d] = packhf(h2, h3);
        *(uint32_t*)&aol[(row0 + 8) * HD + h * DHEAD + d] = packhf(v2 - h2, v3 - h3);
    }
}

// ---------------------------------------------------------------------------
// Launcher
// ---------------------------------------------------------------------------
extern "C" void kernel_launch(void* const* d_in, const int* in_sizes, int n_in,
                              void* d_out, int out_size)
{
    (void)in_sizes; (void)n_in; (void)out_size;

    const float* h_in   = (const float*)d_in[0];
    const float* W_dkv  = (const float*)d_in[1];
    const float* b_dkv  = (const float*)d_in[2];
    const float* W_dq   = (const float*)d_in[3];
    const float* b_dq   = (const float*)d_in[4];
    const float* W_uk   = (const float*)d_in[5];
    const float* b_uk   = (const float*)d_in[6];
    const float* W_uv   = (const float*)d_in[7];
    const float* b_uv   = (const float*)d_in[8];
    const float* W_uq   = (const float*)d_in[9];
    const float* b_uq   = (const float*)d_in[10];
    const float* W_qr   = (const float*)d_in[11];
    const float* b_qr   = (const float*)d_in[12];
    const float* W_kr   = (const float*)d_in[13];
    const float* b_kr   = (const float*)d_in[14];
    const float* W_out  = (const float*)d_in[15];
    const float* b_out  = (const float*)d_in[16];

    float* out_main = (float*)d_out;
    float* out_ckv  = out_main + (size_t)NTOK * EMB;
    float* out_krot = out_ckv + (size_t)NTOK * CLAT;

    __half* bf;
    float *p_qr, *p_kr;
    cudaGetSymbolAddress((void**)&bf, g_bf);
    cudaGetSymbolAddress((void**)&p_qr, g_qr);
    cudaGetSymbolAddress((void**)&p_kr, g_kr);

    int nsm = 148;
    cudaDeviceGetAttribute(&nsm, cudaDevAttrMultiProcessorCount, 0);
    const int nslots = 2 * nsm;

    cudaFuncSetAttribute(bf_gemm_ws, cudaFuncAttributeMaxDynamicSharedMemorySize, GSMEM);
    cudaFuncSetAttribute(attn_mma_kernel, cudaFuncAttributeMaxDynamicSharedMemorySize, ASMEM);

    const float qsc = 0.08838834764831845f;

    // --- one batched split launch ---
    {
        SBatch sbch;
        int acc4 = 0, idx = 0;
        auto add = [&](const float* src, size_t offH, ptrdiff_t offL, size_t n) {
            acc4 += (int)(n / 4);
            sbch.d[idx].src = src;
            sbch.d[idx].hi  = (uint32_t*)(bf + offH);
            sbch.d[idx].lo  = (offL >= 0) ? (uint32_t*)(bf + offL) : nullptr;
            sbch.d[idx].end4 = acc4;
            idx++;
        };
        add(h_in,  OF_HH,   (ptrdiff_t)OF_HL,   (size_t)NTOK * EMB);
        add(W_dkv, OF_DKVH, (ptrdiff_t)OF_DKVL, (size_t)EMB * CLAT);
        add(W_dq,  OF_DQH,  (ptrdiff_t)OF_DQL,  (size_t)EMB * CLAT);
        add(W_kr,  OF_KRH,  (ptrdiff_t)OF_KRL,  (size_t)EMB * (HEADS * DROPE));
        add(W_uk,  OF_UKH,  (ptrdiff_t)OF_UKL,  (size_t)CLAT * (HEADS * SPLIT));
        add(W_uv,  OF_UVH,  (ptrdiff_t)-1,      (size_t)CLAT * HD);
        add(W_uq,  OF_UQH,  (ptrdiff_t)OF_UQL,  (size_t)CLAT * (HEADS * SPLIT));
        add(W_qr,  OF_QRH,  (ptrdiff_t)OF_QRL,  (size_t)CLAT * (HEADS * DROPE));
        add(W_out, OF_OUTH, (ptrdiff_t)-1,      (size_t)HD * EMB);
        sbch.total4 = acc4;
        split_all_kernel<<<(acc4 + 255) / 256, 256>>>(sbch);
    }

    auto mkdesc = [&](const __half* Ah, const __half* Al,
                      const __half* Bh, const __half* Bl,
                      const float* bias, float* Cf, __half* Ch, __half* Cl,
                      int N, int K, int seg, int hstride, int col_off, int ostride,
                      float scale, int two_term) {
        GDesc d;
        d.Ah = Ah; d.Al = Al; d.Bh = Bh; d.Bl = Bl;
        d.bias = bias; d.Cf = Cf; d.Ch = Ch; d.Cl = Cl;
        d.N = N; d.K = K; d.seg = seg; d.hstride = hstride;
        d.col_off = col_off; d.ostride = ostride; d.scale = scale;
        d.two_term = two_term;
        d.tile_end = 0;
        return d;
    };
    auto finalize = [&](GBatch& gb, int nd) {
        int acc = 0;
        for (int i = 0; i < 4; i++) {
            if (i < nd) { acc += (gb.d[i].N / BN) * (NTOK / BM); gb.d[i].tile_end = acc; }
            else        { gb.d[i].tile_end = 0x7fffffff; }
        }
        gb.total = acc;
    };

    // --- stage 1: c_kv, c_q, k_rot_pre (3-term) ---
    {
        GBatch gb;
        gb.d[0] = mkdesc(bf+OF_HH, bf+OF_HL, bf+OF_DKVH, bf+OF_DKVL, b_dkv,
                         out_ckv, bf+OF_CKVH, bf+OF_CKVL,
                         CLAT, EMB, CLAT, CLAT, 0, CLAT, 1.0f, 0);
        gb.d[1] = mkdesc(bf+OF_HH, bf+OF_HL, bf+OF_DQH, bf+OF_DQL, b_dq,
                         nullptr, bf+OF_CQH, bf+OF_CQL,
                         CLAT, EMB, CLAT, CLAT, 0, CLAT, 1.0f, 0);
        gb.d[2] = mkdesc(bf+OF_HH, bf+OF_HL, bf+OF_KRH, bf+OF_KRL, b_kr,
                         p_kr, nullptr, nullptr,
                         HEADS*DROPE, EMB, HEADS*DROPE, HEADS*DROPE, 0, HEADS*DROPE, 1.0f, 0);
        finalize(gb, 3);
        int grid = gb.total < nslots ? gb.total : nslots;
        bf_gemm_ws<<<grid, 128, GSMEM>>>(gb);
    }
    // --- stage 2: uk (3t), uv (2t, hi-only), uq (3t), qr (3t) ---
    {
        GBatch gb;
        gb.d[0] = mkdesc(bf+OF_CKVH, bf+OF_CKVL, bf+OF_UKH, bf+OF_UKL, b_uk,
                         nullptr, bf+OF_KH, bf+OF_KL,
                         HEADS*SPLIT, CLAT, SPLIT, DHEAD, 0, HD, 1.0f, 0);
        gb.d[1] = mkdesc(bf+OF_CKVH, bf+OF_CKVL, bf+OF_UVH, nullptr, b_uv,
                         nullptr, bf+OF_VH, nullptr,
                         HD, CLAT, HD, HD, 0, HD, 1.0f, 1);
        gb.d[2] = mkdesc(bf+OF_CQH, bf+OF_CQL, bf+OF_UQH, bf+OF_UQL, b_uq,
                         nullptr, bf+OF_QH, bf+OF_QL,
                         HEADS*SPLIT, CLAT, SPLIT, DHEAD, 0, HD, qsc, 0);
        gb.d[3] = mkdesc(bf+OF_CQH, bf+OF_CQL, bf+OF_QRH, bf+OF_QRL, b_qr,
                         p_qr, nullptr, nullptr,
                         HEADS*DROPE, CLAT, HEADS*DROPE, HEADS*DROPE, 0, HEADS*DROPE, 1.0f, 0);
        finalize(gb, 4);
        int grid = gb.total < nslots ? gb.total : nslots;
        bf_gemm_ws<<<grid, 128, GSMEM>>>(gb);
    }
    // --- rotary ---
    rotary_kernel<<<(2*NTOK*HEADS + 255)/256, 256>>>(
        p_qr, p_kr, bf+OF_QH, bf+OF_QL, bf+OF_KH, bf+OF_KL, out_krot);
    // --- attention (round-10 geometry) ---
    attn_mma_kernel<<<dim3(SEQ/AM, BATCH*HEADS), 256, ASMEM>>>(
        bf+OF_QH, bf+OF_QL, bf+OF_KH, bf+OF_KL, bf+OF_VH,
        bf+OF_AOH, bf+OF_AOL);
    // --- stage 3: out-projection (2-term) ---
    {
        GBatch gb;
        gb.d[0] = mkdesc(bf+OF_AOH, bf+OF_AOL, bf+OF_OUTH, nullptr, b_out,
                         out_main, nullptr, nullptr,
                         EMB, HD, EMB, EMB, 0, EMB, 1.0f, 1);
        finalize(gb, 1);
        int grid = gb.total < nslots ? gb.total : nslots;
        bf_gemm_ws<<<grid, 128, GSMEM>>>(gb);
    }
}

// round 14
// speedup vs baseline: 1.1155x; 1.1155x over previous
#include <cuda_runtime.h>
#include <cuda_fp16.h>
#include <math.h>
#include <cstdint>

// Problem constants
#define BATCH 2
#define SEQ   2048
#define EMB   2048
#define HEADS 16
#define DHEAD 128
#define DROPE 32
#define SPLIT 96
#define CLAT  512
#define NTOK  (BATCH*SEQ)          // 4096
#define HD    (HEADS*DHEAD)        // 2048

// ---------------------------------------------------------------------------
// Global scratch (fp16 planes)
// ---------------------------------------------------------------------------
constexpr size_t OF_HH   = 0;
constexpr size_t OF_HL   = OF_HH   + (size_t)NTOK*EMB;
constexpr size_t OF_DKVH = OF_HL   + (size_t)NTOK*EMB;
constexpr size_t OF_DKVL = OF_DKVH + (size_t)EMB*CLAT;
constexpr size_t OF_DQH  = OF_DKVL + (size_t)EMB*CLAT;
constexpr size_t OF_DQL  = OF_DQH  + (size_t)EMB*CLAT;
constexpr size_t OF_KRH  = OF_DQL  + (size_t)EMB*CLAT;
constexpr size_t OF_KRL  = OF_KRH  + (size_t)EMB*(HEADS*DROPE);
constexpr size_t OF_UKH  = OF_KRL  + (size_t)EMB*(HEADS*DROPE);
constexpr size_t OF_UKL  = OF_UKH  + (size_t)CLAT*(HEADS*SPLIT);
constexpr size_t OF_UVH  = OF_UKL  + (size_t)CLAT*(HEADS*SPLIT);
constexpr size_t OF_UQH  = OF_UVH  + (size_t)CLAT*HD;
constexpr size_t OF_UQL  = OF_UQH  + (size_t)CLAT*(HEADS*SPLIT);
constexpr size_t OF_QRH  = OF_UQL  + (size_t)CLAT*(HEADS*SPLIT);
constexpr size_t OF_QRL  = OF_QRH  + (size_t)CLAT*(HEADS*DROPE);
constexpr size_t OF_OUTH = OF_QRL  + (size_t)CLAT*(HEADS*DROPE);
constexpr size_t OF_CKVH = OF_OUTH + (size_t)HD*EMB;
constexpr size_t OF_CKVL = OF_CKVH + (size_t)NTOK*CLAT;
constexpr size_t OF_CQH  = OF_CKVL + (size_t)NTOK*CLAT;
constexpr size_t OF_CQL  = OF_CQH  + (size_t)NTOK*CLAT;
constexpr size_t OF_QH   = OF_CQL  + (size_t)NTOK*CLAT;
constexpr size_t OF_QL   = OF_QH   + (size_t)NTOK*HD;
constexpr size_t OF_KH   = OF_QL   + (size_t)NTOK*HD;
constexpr size_t OF_KL   = OF_KH   + (size_t)NTOK*HD;
constexpr size_t OF_VH   = OF_KL   + (size_t)NTOK*HD;
constexpr size_t OF_AOH  = OF_VH   + (size_t)NTOK*HD;
constexpr size_t OF_AOL  = OF_AOH  + (size_t)NTOK*HD;
constexpr size_t BF_TOTAL= OF_AOL  + (size_t)NTOK*HD;

__device__ __half g_bf[BF_TOTAL];
__device__ float g_qr[NTOK * HEADS * DROPE];
__device__ float g_kr[NTOK * HEADS * DROPE];
// [0]=ticket stage12, [1]=ticket stage3, [2]=ckv_done, [3]=cq_done
__device__ int   g_sync[4];

// ---------------------------------------------------------------------------
// Helpers
// ---------------------------------------------------------------------------
__device__ __forceinline__ uint32_t smem_u32(const void* p) {
    uint32_t a;
    asm("{ .reg .u64 t; cvta.to.shared.u64 t, %1; cvt.u32.u64 %0, t; }"
        : "=r"(a) : "l"(p));
    return a;
}
__device__ __forceinline__ uint32_t packhf(float e0, float e1) {
    uint32_t r;
    asm("cvt.rn.f16x2.f32 %0, %1, %2;" : "=r"(r) : "f"(e1), "f"(e0));
    return r;
}
__device__ __forceinline__ float hrt(float x) {
    return __half2float(__float2half_rn(x));
}
__device__ __forceinline__ void ldsm_x4(uint32_t& r0, uint32_t& r1, uint32_t& r2,
                                        uint32_t& r3, uint32_t addr) {
    asm volatile("ldmatrix.sync.aligned.m8n8.x4.shared.b16 {%0,%1,%2,%3}, [%4];"
                 : "=r"(r0), "=r"(r1), "=r"(r2), "=r"(r3) : "r"(addr));
}
__device__ __forceinline__ void ldsm_x4t(uint32_t& r0, uint32_t& r1, uint32_t& r2,
                                         uint32_t& r3, uint32_t addr) {
    asm volatile("ldmatrix.sync.aligned.m8n8.x4.trans.shared.b16 {%0,%1,%2,%3}, [%4];"
                 : "=r"(r0), "=r"(r1), "=r"(r2), "=r"(r3) : "r"(addr));
}
__device__ __forceinline__ void mma_f16(float* d, const uint32_t* a, const uint32_t* b) {
    asm volatile(
        "mma.sync.aligned.m16n8k16.row.col.f32.f16.f16.f32 "
        "{%0,%1,%2,%3}, {%4,%5,%6,%7}, {%8,%9}, {%0,%1,%2,%3};"
        : "+f"(d[0]), "+f"(d[1]), "+f"(d[2]), "+f"(d[3])
        : "r"(a[0]), "r"(a[1]), "r"(a[2]), "r"(a[3]), "r"(b[0]), "r"(b[1]));
}
__device__ __forceinline__ void cp16(uint32_t saddr, const void* gaddr) {
    asm volatile("cp.async.cg.shared.global [%0], [%1], 16;" :: "r"(saddr), "l"(gaddr));
}
__device__ __forceinline__ void cp_commit() {
    asm volatile("cp.async.commit_group;" ::: "memory");
}
template<int N> __device__ __forceinline__ void cp_wait() {
    asm volatile("cp.async.wait_group %0;" :: "n"(N) : "memory");
}

// ---------------------------------------------------------------------------
// Batched fp32 -> fp16 hi/lo split kernel (lo optional) + sync-counter reset
// ---------------------------------------------------------------------------
struct SDesc { const float* src; uint32_t* hi; uint32_t* lo; int end4; };
struct SBatch { SDesc d[9]; int total4; };

__global__ void split_all_kernel(SBatch sb)
{
    if (blockIdx.x == 0 && threadIdx.x < 4) g_sync[threadIdx.x] = 0;
    int i = blockIdx.x * blockDim.x + threadIdx.x;
    if (i >= sb.total4) return;
    int g = 0;
    while (i >= sb.d[g].end4) g++;
    int start = (g == 0) ? 0 : sb.d[g-1].end4;
    int li = i - start;
    float4 v = ((const float4*)sb.d[g].src)[li];
    float h0 = hrt(v.x), h1 = hrt(v.y), h2 = hrt(v.z), h3 = hrt(v.w);
    sb.d[g].hi[li*2]   = packhf(h0, h1);
    sb.d[g].hi[li*2+1] = packhf(h2, h3);
    if (sb.d[g].lo) {
        sb.d[g].lo[li*2]   = packhf(v.x - h0, v.y - h1);
        sb.d[g].lo[li*2+1] = packhf(v.z - h2, v.w - h3);
    }
}

// ---------------------------------------------------------------------------
// Persistent multi-GEMM with dynamic ticket queue + dependency counters.
// CTA 128x128, 128 threads, warp 64x64, BK=32, double-buffered cp.async,
// 2 CTAs/SM, 3- or 2-term fp16.
// dep: 0 none, 1 wait ckv_done==128, 2 wait cq_done==128
// sig: 0 none, 1 bump ckv_done, 2 bump cq_done
// ---------------------------------------------------------------------------
#define BM 128
#define BN 128
#define BK 32
#define PA 40
#define PB 136
#define A_PLANE (BM*PA*2)
#define B_PLANE (BK*PB*2)
#define OFF_AHI 0
#define OFF_ALO (A_PLANE)
#define OFF_BHI (2*A_PLANE)
#define OFF_BLO (2*A_PLANE + B_PLANE)
#define SBUF    (2*A_PLANE + 2*B_PLANE)
#define GSMEM   (2*SBUF)
#define DEP_TARGET 128

struct GDesc {
    const __half *Ah, *Al, *Bh, *Bl;
    const float* bias;
    float* Cf;
    __half *Ch, *Cl;
    int N, K, seg, hstride, col_off, ostride;
    float scale;
    int two_term;
    int dep, sig;
    int tile_end;
};
struct GBatch { GDesc d[8]; int total; };

__device__ __forceinline__ void gemm_issue(
    const __half* Ah, const __half* Al,
    const __half* Bh, const __half* Bl, int two_term,
    int m0, int n0, int kk, int K, int N, uint32_t base, int t)
{
#pragma unroll
    for (int i = 0; i < 4; i++) {
        int f = t + i * 128;
        int m = f >> 2, g = f & 3;
        size_t gi = (size_t)(m0 + m) * K + kk + g * 8;
        uint32_t so = (uint32_t)(m * (PA*2) + g * 16);
        cp16(base + OFF_AHI + so, Ah + gi);
        cp16(base + OFF_ALO + so, Al + gi);
    }
#pragma unroll
    for (int i = 0; i < 4; i++) {
        int f = t + i * 128;
        int k2 = f >> 4, nc = f & 15;
        size_t gi = (size_t)(kk + k2) * N + n0 + nc * 8;
        uint32_t so = (uint32_t)(k2 * (PB*2) + nc * 16);
        cp16(base + OFF_BHI + so, Bh + gi);
        if (!two_term) cp16(base + OFF_BLO + so, Bl + gi);
    }
}

__global__ __launch_bounds__(128, 2)
void bf_gemm_ws(GBatch batch, int tk)
{
    extern __shared__ char smc[];
    __shared__ int s_tile;
    const uint32_t sb = smem_u32(smc);
    const int t    = threadIdx.x;
    const int lane = t & 31;
    const int w    = t >> 5;
    const int wm   = (w >> 1) * 64;
    const int wn   = (w & 1) * 64;

    const uint32_t aLane = (uint32_t)((wm + (lane & 15)) * PA + (lane >> 4) * 8) * 2;
    const uint32_t bLaneRow = (uint32_t)(lane & 15) * (PB * 2);
    const uint32_t bLaneCol = (uint32_t)(wn + (lane >> 4) * 8) * 2;

    for (;;) {
        __syncthreads();
        if (t == 0) s_tile = atomicAdd(&g_sync[tk], 1);
        __syncthreads();
        const int tile = s_tile;
        if (tile >= batch.total) break;

        int g = 0;
        while (tile >= batch.d[g].tile_end) g++;
        const GDesc& d = batch.d[g];
        const int tbase = (g == 0) ? 0 : batch.d[g-1].tile_end;
        const int lt  = tile - tbase;
        const int ntn = d.N / BN;
        const int m0  = (lt / ntn) * BM;
        const int n0  = (lt % ntn) * BN;
        const int NC  = d.K / BK;
        const int twot = d.two_term;

        // dependency wait
        if (d.dep) {
            if (t == 0) {
                while (atomicAdd(&g_sync[d.dep + 1], 0) < DEP_TARGET)
                    __nanosleep(64);
            }
            __syncthreads();
        }

        float acc[4][8][4];
#pragma unroll
        for (int i = 0; i < 4; i++)
#pragma unroll
            for (int j = 0; j < 8; j++)
#pragma unroll
                for (int r = 0; r < 4; r++) acc[i][j][r] = 0.f;

        gemm_issue(d.Ah, d.Al, d.Bh, d.Bl, twot, m0, n0, 0, d.K, d.N, sb, t);
        cp_commit();

        for (int ch = 0; ch < NC; ch++) {
            if (ch + 1 < NC) {
                gemm_issue(d.Ah, d.Al, d.Bh, d.Bl, twot, m0, n0, (ch + 1) * BK, d.K, d.N,
                           sb + (uint32_t)((ch + 1) & 1) * SBUF, t);
                cp_commit();
                cp_wait<1>();
            } else {
                cp_wait<0>();
            }
            __syncthreads();

            const uint32_t base = sb + (uint32_t)(ch & 1) * SBUF;
#pragma unroll
            for (int ks = 0; ks < 2; ks++) {
                uint32_t Fah[4][4], Fal[4][4];
                const uint32_t aOff = aLane + (uint32_t)ks * 32;
#pragma unroll
                for (int mt = 0; mt < 4; mt++) {
                    uint32_t ad = base + aOff + (uint32_t)mt * (16 * PA * 2);
                    ldsm_x4(Fah[mt][0], Fah[mt][1], Fah[mt][2], Fah[mt][3], ad + OFF_AHI);
                    ldsm_x4(Fal[mt][0], Fal[mt][1], Fal[mt][2], Fal[mt][3], ad + OFF_ALO);
                }
                const uint32_t bOff = bLaneRow + (uint32_t)ks * (16 * PB * 2) + bLaneCol;
                if (twot) {
#pragma unroll
                    for (int np = 0; np < 4; np++) {
                        uint32_t Bh[4];
                        uint32_t bd = base + bOff + (uint32_t)np * 32;
                        ldsm_x4t(Bh[0], Bh[1], Bh[2], Bh[3], bd + OFF_BHI);
#pragma unroll
                        for (int mt = 0; mt < 4; mt++) {
                            mma_f16(acc[mt][2*np],   Fah[mt], &Bh[0]);
                            mma_f16(acc[mt][2*np],   Fal[mt], &Bh[0]);
                            mma_f16(acc[mt][2*np+1], Fah[mt], &Bh[2]);
                            mma_f16(acc[mt][2*np+1], Fal[mt], &Bh[2]);
                        }
                    }
                } else {
#pragma unroll
                    for (int np = 0; np < 4; np++) {
                        uint32_t Bh[4], Bl[4];
                        uint32_t bd = base + bOff + (uint32_t)np * 32;
                        ldsm_x4t(Bh[0], Bh[1], Bh[2], Bh[3], bd + OFF_BHI);
                        ldsm_x4t(Bl[0], Bl[1], Bl[2], Bl[3], bd + OFF_BLO);
#pragma unroll
                        for (int mt = 0; mt < 4; mt++) {
                            mma_f16(acc[mt][2*np],   Fah[mt], &Bh[0]);
                            mma_f16(acc[mt][2*np],   Fah[mt], &Bl[0]);
                            mma_f16(acc[mt][2*np],   Fal[mt], &Bh[0]);
                            mma_f16(acc[mt][2*np+1], Fah[mt], &Bh[2]);
                            mma_f16(acc[mt][2*np+1], Fah[mt], &Bl[2]);
                            mma_f16(acc[mt][2*np+1], Fal[mt], &Bh[2]);
                        }
                    }
                }
            }
            __syncthreads();
        }

        // Epilogue
        const int r0 = lane >> 2;
        const int c0 = (lane & 3) * 2;
#pragma unroll
        for (int mt = 0; mt < 4; mt++) {
#pragma unroll
            for (int nt = 0; nt < 8; nt++) {
                int n = n0 + wn + nt * 8 + c0;
                int oc = (n / d.seg) * d.hstride + (n % d.seg) + d.col_off;
                float b0 = d.bias[n], b1 = d.bias[n + 1];
                int mrow0 = m0 + wm + mt * 16 + r0;
#pragma unroll
                for (int half = 0; half < 2; half++) {
                    size_t row = (size_t)(mrow0 + half * 8);
                    float v0 = (acc[mt][nt][half*2]   + b0) * d.scale;
                    float v1 = (acc[mt][nt][half*2+1] + b1) * d.scale;
                    if (d.Cf) *(float2*)&d.Cf[row * d.ostride + oc] = make_float2(v0, v1);
                    if (d.Ch) {
                        float h0 = hrt(v0), h1 = hrt(v1);
                        *(uint32_t*)&d.Ch[row * d.ostride + oc] = packhf(h0, h1);
                        if (d.Cl)
                            *(uint32_t*)&d.Cl[row * d.ostride + oc] = packhf(v0 - h0, v1 - h1);
                    }
                }
            }
        }

        // signal completion
        __syncthreads();
        if (d.sig && t == 0) {
            __threadfence();
            atomicAdd(&g_sync[d.sig + 1], 1);
        }
    }
}

// ---------------------------------------------------------------------------
// Rotary: __sincosf + vectorized uint4 plane stores
// ---------------------------------------------------------------------------
__global__ void rotary_kernel(const float* __restrict__ qr,
                              const float* __restrict__ kr,
                              __half* __restrict__ qh, __half* __restrict__ ql,
                              __half* __restrict__ kh, __half* __restrict__ kl,
                              float* __restrict__ krot_out)
{
    int gid = blockIdx.x * blockDim.x + threadIdx.x;
    if (gid >= 2 * NTOK * HEADS) return;
    const bool isK = gid >= NTOK * HEADS;
    int idx = isK ? (gid - NTOK * HEADS) : gid;
    int h   = idx & (HEADS - 1);
    int tok = idx >> 4;
    int s   = tok & (SEQ - 1);
    float tpos = (float)s / 40.0f;
    const float qscale = 0.08838834764831845f;

    const float* src = isK ? kr : qr;
    float x[32];
#pragma unroll
    for (int i = 0; i < 8; i++) {
        float4 a = *(const float4*)&src[(size_t)idx * 32 + i * 4];
        x[i*4+0]=a.x; x[i*4+1]=a.y; x[i*4+2]=a.z; x[i*4+3]=a.w;
    }

    float y[32];
#pragma unroll
    for (int j = 0; j < 8; j++) {
        float invf = exp2f(-1.6609640474436813f * (float)j);
        float ang = tpos * invf;
        float sj, cj;
        __sincosf(ang, &sj, &cj);
        y[j]     = x[j] * cj - x[j + 8] * sj;
        y[j + 8] = x[j + 8] * cj + x[j] * sj;
    }
#pragma unroll
    for (int d = 16; d < 32; d++) y[d] = x[d];

    const float osc = isK ? 1.0f : qscale;
    uint32_t ph[16], pl[16];
#pragma unroll
    for (int j = 0; j < 16; j++) {
        float v0 = y[2*j] * osc, v1 = y[2*j+1] * osc;
        float h0 = hrt(v0), h1 = hrt(v1);
        ph[j] = packhf(h0, h1);
        pl[j] = packhf(v0 - h0, v1 - h1);
    }

    size_t obase = (size_t)tok * HD + h * DHEAD + SPLIT;
    __half* dsth = isK ? kh : qh;
    __half* dstl = isK ? kl : ql;
#pragma unroll
    for (int i = 0; i < 4; i++) {
        *(uint4*)&dsth[obase + 8*i] = make_uint4(ph[4*i], ph[4*i+1], ph[4*i+2], ph[4*i+3]);
        *(uint4*)&dstl[obase + 8*i] = make_uint4(pl[4*i], pl[4*i+1], pl[4*i+2], pl[4*i+3]);
    }
    if (isK) {
#pragma unroll
        for (int i = 0; i < 8; i++)
            *(float4*)&krot_out[(size_t)idx * 32 + i * 4] =
                make_float4(y[i*4], y[i*4+1], y[i*4+2], y[i*4+3]);
    }
}

// ---------------------------------------------------------------------------
// Causal flash-attention: AM=128, 256 threads, double-buffered 3-plane KV
// (Khi,Klo,Vhi), QK 3-term, PV 2-term.
// ---------------------------------------------------------------------------
#define AM 128
#define AN 64
#define APH 136
#define AQHI 0
#define AQLO (AM*APH*2)
#define AKV0 (2*AM*APH*2)
#define KVP  (AN*APH*2)
#define KVBUF (3*KVP)
#define ASMEM (AKV0 + 2*KVBUF)           // 174080

__device__ __forceinline__ void attn_issue_kv(
    const __half* kh, const __half* kl, const __half* vh,
    size_t rowbase, uint32_t kvbase, int t)
{
#pragma unroll
    for (int i = 0; i < 4; i++) {
        int f = t + i * 256;
        int row = f >> 4, ch = f & 15;
        size_t gi = (rowbase + row) * HD + ch * 8;
        uint32_t so = (uint32_t)(row * 272 + ch * 16);
        cp16(kvbase + 0*KVP + so, kh + gi);
        cp16(kvbase + 1*KVP + so, kl + gi);
        cp16(kvbase + 2*KVP + so, vh + gi);
    }
}

__global__ __launch_bounds__(256, 1)
void attn_mma_kernel(const __half* __restrict__ qh, const __half* __restrict__ ql,
                     const __half* __restrict__ kh, const __half* __restrict__ kl,
                     const __half* __restrict__ vh,
                     __half* __restrict__ aoh, __half* __restrict__ aol)
{
    extern __shared__ char smc[];
    const uint32_t sb = smem_u32(smc);
    const int t    = threadIdx.x;
    const int lane = t & 31;
    const int w    = t >> 5;
    const int bh   = blockIdx.y;
    const int b    = bh >> 4;
    const int h    = bh & 15;
    const int q0   = ((int)gridDim.x - 1 - (int)blockIdx.x) * AM;

    const size_t qrowbase = (size_t)(b * SEQ + q0);
    const __half* qhp = qh + h * DHEAD;
    const __half* qlp = ql + h * DHEAD;
    const __half* khp = kh + h * DHEAD;
    const __half* klp = kl + h * DHEAD;
    const __half* vhp = vh + h * DHEAD;

#pragma unroll
    for (int i = 0; i < 8; i++) {
        int f = t + i * 256;
        int row = f >> 4, ch = f & 15;
        size_t gi = (qrowbase + row) * HD + ch * 8;
        uint32_t so = (uint32_t)(row * 272 + ch * 16);
        cp16(sb + AQHI + so, qhp + gi);
        cp16(sb + AQLO + so, qlp + gi);
    }
    attn_issue_kv(khp, klp, vhp, (size_t)(b * SEQ), sb + AKV0, t);
    cp_commit();

    float mrow[2] = {-INFINITY, -INFINITY};
    float lrow[2] = {0.f, 0.f};
    float O[16][4];
#pragma unroll
    for (int i = 0; i < 16; i++)
#pragma unroll
        for (int r = 0; r < 4; r++) O[i][r] = 0.f;

    const int ntiles = q0 / AN + 2;
    for (int nt = 0; nt < ntiles; nt++) {
        const int n0 = nt * AN;
        if (nt + 1 < ntiles) {
            attn_issue_kv(khp, klp, vhp, (size_t)(b * SEQ + (nt + 1) * AN),
                          sb + AKV0 + (uint32_t)((nt + 1) & 1) * KVBUF, t);
            cp_commit();
            cp_wait<1>();
        } else {
            cp_wait<0>();
        }
        __syncthreads();

        const uint32_t kvb = sb + AKV0 + (uint32_t)(nt & 1) * KVBUF;
        const bool active = (q0 + w * 16 + 15) >= n0;
        if (active) {
            float S[8][4];
#pragma unroll
            for (int nf = 0; nf < 8; nf++)
#pragma unroll
                for (int r = 0; r < 4; r++) S[nf][r] = 0.f;

#pragma unroll
            for (int ks = 0; ks < 8; ks++) {
                uint32_t ah[4], al[4];
                uint32_t ad = sb + (uint32_t)((w * 16 + (lane & 15)) * APH
                                              + ks * 16 + (lane >> 4) * 8) * 2;
                ldsm_x4(ah[0], ah[1], ah[2], ah[3], ad + AQHI);
                ldsm_x4(al[0], al[1], al[2], al[3], ad + AQLO);
#pragma unroll
                for (int g = 0; g < 4; g++) {
                    uint32_t bd = kvb + (uint32_t)((g * 16 + (lane & 7) + (lane >> 4) * 8) * APH
                                                   + ks * 16 + ((lane >> 3) & 1) * 8) * 2;
                    uint32_t khf[4], klf[4];
                    ldsm_x4(khf[0], khf[1], khf[2], khf[3], bd + 0*KVP);
                    ldsm_x4(klf[0], klf[1], klf[2], klf[3], bd + 1*KVP);
                    mma_f16(S[2*g],   ah, &khf[0]);
                    mma_f16(S[2*g],   ah, &klf[0]);
                    mma_f16(S[2*g],   al, &khf[0]);
                    mma_f16(S[2*g+1], ah, &khf[2]);
                    mma_f16(S[2*g+1], ah, &klf[2]);
                    mma_f16(S[2*g+1], al, &khf[2]);
                }
            }

            if (n0 + AN - 1 > q0 + w * 16) {
                int grow0 = q0 + w * 16 + (lane >> 2);
#pragma unroll
                for (int nf = 0; nf < 8; nf++) {
                    int col = n0 + nf * 8 + (lane & 3) * 2;
#pragma unroll
                    for (int r = 0; r < 4; r++) {
                        int gr = grow0 + (r >> 1) * 8;
                        int gc = col + (r & 1);
                        if (gc > gr) S[nf][r] = -INFINITY;
                    }
                }
            }

            float corr[2];
#pragma unroll
            for (int rr = 0; rr < 2; rr++) {
                float rm = -INFINITY;
#pragma unroll
                for (int nf = 0; nf < 8; nf++)
                    rm = fmaxf(rm, fmaxf(S[nf][rr*2], S[nf][rr*2+1]));
                rm = fmaxf(rm, __shfl_xor_sync(0xffffffffu, rm, 1));
                rm = fmaxf(rm, __shfl_xor_sync(0xffffffffu, rm, 2));
                float mnew = fmaxf(mrow[rr], rm);
                corr[rr] = __expf(mrow[rr] - mnew);
                float rs = 0.f;
#pragma unroll
                for (int nf = 0; nf < 8; nf++) {
                    float p0 = __expf(S[nf][rr*2]   - mnew);
                    float p1 = __expf(S[nf][rr*2+1] - mnew);
                    S[nf][rr*2]   = p0;
                    S[nf][rr*2+1] = p1;
                    rs += p0 + p1;
                }
                rs += __shfl_xor_sync(0xffffffffu, rs, 1);
                rs += __shfl_xor_sync(0xffffffffu, rs, 2);
                lrow[rr] = lrow[rr] * corr[rr] + rs;
                mrow[rr] = mnew;
            }
#pragma unroll
            for (int i = 0; i < 16; i++) {
                O[i][0] *= corr[0]; O[i][1] *= corr[0];
                O[i][2] *= corr[1]; O[i][3] *= corr[1];
            }

#pragma unroll
            for (int j = 0; j < 4; j++) {
                uint32_t ph[4], pl[4];
                {
                    float s00 = S[2*j][0],   s01 = S[2*j][1],   s02 = S[2*j][2],   s03 = S[2*j][3];
                    float s10 = S[2*j+1][0], s11 = S[2*j+1][1], s12 = S[2*j+1][2], s13 = S[2*j+1][3];
                    float h00 = hrt(s00), h01 = hrt(s01), h02 = hrt(s02), h03 = hrt(s03);
                    float h10 = hrt(s10), h11 = hrt(s11), h12 = hrt(s12), h13 = hrt(s13);
                    ph[0] = packhf(h00, h01); ph[1] = packhf(h02, h03);
                    ph[2] = packhf(h10, h11); ph[3] = packhf(h12, h13);
                    pl[0] = packhf(s00 - h00, s01 - h01); pl[1] = packhf(s02 - h02, s03 - h03);
                    pl[2] = packhf(s10 - h10, s11 - h11); pl[3] = packhf(s12 - h12, s13 - h13);
                }
#pragma unroll
                for (int g = 0; g < 8; g++) {
                    uint32_t vd = kvb + (uint32_t)((j * 16 + (lane & 15)) * APH
                                                   + g * 16 + (lane >> 4) * 8) * 2;
                    uint32_t vhf[4];
                    ldsm_x4t(vhf[0], vhf[1], vhf[2], vhf[3], vd + 2*KVP);
                    mma_f16(O[2*g],   ph, &vhf[0]);
                    mma_f16(O[2*g],   pl, &vhf[0]);
                    mma_f16(O[2*g+1], ph, &vhf[2]);
                    mma_f16(O[2*g+1], pl, &vhf[2]);
                }
            }
        }
        __syncthreads();
    }

    float inv0 = 1.0f / lrow[0];
    float inv1 = 1.0f / lrow[1];
#pragma unroll
    for (int nd = 0; nd < 16; nd++) {
        int d = nd * 8 + (lane & 3) * 2;
        size_t row0 = (size_t)(b * SEQ + q0 + w * 16 + (lane >> 2));
        float v0 = O[nd][0] * inv0, v1 = O[nd][1] * inv0;
        float h0 = hrt(v0), h1 = hrt(v1);
        *(uint32_t*)&aoh[row0 * HD + h * DHEAD + d] = packhf(h0, h1);
        *(uint32_t*)&aol[row0 * HD + h * DHEAD + d] = packhf(v0 - h0, v1 - h1);
        float v2 = O[nd][2] * inv1, v3 = O[nd][3] * inv1;
        float h2 = hrt(v2), h3 = hrt(v3);
        *(uint32_t*)&aoh[(row0 + 8) * HD + h * DHEAD + d] = packhf(h2, h3);
        *(uint32_t*)&aol[(row0 + 8) * HD + h * DHEAD + d] = packhf(v2 - h2, v3 - h3);
    }
}

// ---------------------------------------------------------------------------
// Launcher
// ---------------------------------------------------------------------------
extern "C" void kernel_launch(void* const* d_in, const int* in_sizes, int n_in,
                              void* d_out, int out_size)
{
    (void)in_sizes; (void)n_in; (void)out_size;

    const float* h_in   = (const float*)d_in[0];
    const float* W_dkv  = (const float*)d_in[1];
    const float* b_dkv  = (const float*)d_in[2];
    const float* W_dq   = (const float*)d_in[3];
    const float* b_dq   = (const float*)d_in[4];
    const float* W_uk   = (const float*)d_in[5];
    const float* b_uk   = (const float*)d_in[6];
    const float* W_uv   = (const float*)d_in[7];
    const float* b_uv   = (const float*)d_in[8];
    const float* W_uq   = (const float*)d_in[9];
    const float* b_uq   = (const float*)d_in[10];
    const float* W_qr   = (const float*)d_in[11];
    const float* b_qr   = (const float*)d_in[12];
    const float* W_kr   = (const float*)d_in[13];
    const float* b_kr   = (const float*)d_in[14];
    const float* W_out  = (const float*)d_in[15];
    const float* b_out  = (const float*)d_in[16];

    float* out_main = (float*)d_out;
    float* out_ckv  = out_main + (size_t)NTOK * EMB;
    float* out_krot = out_ckv + (size_t)NTOK * CLAT;

    __half* bf;
    float *p_qr, *p_kr;
    cudaGetSymbolAddress((void**)&bf, g_bf);
    cudaGetSymbolAddress((void**)&p_qr, g_qr);
    cudaGetSymbolAddress((void**)&p_kr, g_kr);

    int nsm = 148;
    cudaDeviceGetAttribute(&nsm, cudaDevAttrMultiProcessorCount, 0);
    const int nslots = 2 * nsm;

    cudaFuncSetAttribute(bf_gemm_ws, cudaFuncAttributeMaxDynamicSharedMemorySize, GSMEM);
    cudaFuncSetAttribute(attn_mma_kernel, cudaFuncAttributeMaxDynamicSharedMemorySize, ASMEM);

    const float qsc = 0.08838834764831845f;

    // --- one batched split launch (also zeroes g_sync) ---
    {
        SBatch sbch;
        int acc4 = 0, idx = 0;
        auto add = [&](const float* src, size_t offH, ptrdiff_t offL, size_t n) {
            acc4 += (int)(n / 4);
            sbch.d[idx].src = src;
            sbch.d[idx].hi  = (uint32_t*)(bf + offH);
            sbch.d[idx].lo  = (offL >= 0) ? (uint32_t*)(bf + offL) : nullptr;
            sbch.d[idx].end4 = acc4;
            idx++;
        };
        add(h_in,  OF_HH,   (ptrdiff_t)OF_HL,   (size_t)NTOK * EMB);
        add(W_dkv, OF_DKVH, (ptrdiff_t)OF_DKVL, (size_t)EMB * CLAT);
        add(W_dq,  OF_DQH,  (ptrdiff_t)OF_DQL,  (size_t)EMB * CLAT);
        add(W_kr,  OF_KRH,  (ptrdiff_t)OF_KRL,  (size_t)EMB * (HEADS * DROPE));
        add(W_uk,  OF_UKH,  (ptrdiff_t)OF_UKL,  (size_t)CLAT * (HEADS * SPLIT));
        add(W_uv,  OF_UVH,  (ptrdiff_t)-1,      (size_t)CLAT * HD);
        add(W_uq,  OF_UQH,  (ptrdiff_t)OF_UQL,  (size_t)CLAT * (HEADS * SPLIT));
        add(W_qr,  OF_QRH,  (ptrdiff_t)OF_QRL,  (size_t)CLAT * (HEADS * DROPE));
        add(W_out, OF_OUTH, (ptrdiff_t)-1,      (size_t)HD * EMB);
        sbch.total4 = acc4;
        split_all_kernel<<<(acc4 + 255) / 256, 256>>>(sbch);
    }

    auto mkdesc = [&](const __half* Ah, const __half* Al,
                      const __half* Bh, const __half* Bl,
                      const float* bias, float* Cf, __half* Ch, __half* Cl,
                      int N, int K, int seg, int hstride, int col_off, int ostride,
                      float scale, int two_term, int dep, int sig) {
        GDesc d;
        d.Ah = Ah; d.Al = Al; d.Bh = Bh; d.Bl = Bl;
        d.bias = bias; d.Cf = Cf; d.Ch = Ch; d.Cl = Cl;
        d.N = N; d.K = K; d.seg = seg; d.hstride = hstride;
        d.col_off = col_off; d.ostride = ostride; d.scale = scale;
        d.two_term = two_term; d.dep = dep; d.sig = sig;
        d.tile_end = 0;
        return d;
    };
    auto finalize = [&](GBatch& gb, int nd) {
        int acc = 0;
        for (int i = 0; i < 8; i++) {
            if (i < nd) { acc += (gb.d[i].N / BN) * (NTOK / BM); gb.d[i].tile_end = acc; }
            else        { gb.d[i].tile_end = 0x7fffffff; }
        }
        gb.total = acc;
    };

    // --- fused stage1+stage2 with dynamic ticket + dependencies ---
    {
        GBatch gb;
        // stage1 (all independent; first 384 tickets)
        gb.d[0] = mkdesc(bf+OF_HH, bf+OF_HL, bf+OF_DKVH, bf+OF_DKVL, b_dkv,
                         out_ckv, bf+OF_CKVH, bf+OF_CKVL,
                         CLAT, EMB, CLAT, CLAT, 0, CLAT, 1.0f, 0, /*dep*/0, /*sig*/1);
        gb.d[1] = mkdesc(bf+OF_HH, bf+OF_HL, bf+OF_DQH, bf+OF_DQL, b_dq,
                         nullptr, bf+OF_CQH, bf+OF_CQL,
                         CLAT, EMB, CLAT, CLAT, 0, CLAT, 1.0f, 0, 0, 2);
        gb.d[2] = mkdesc(bf+OF_HH, bf+OF_HL, bf+OF_KRH, bf+OF_KRL, b_kr,
                         p_kr, nullptr, nullptr,
                         HEADS*DROPE, EMB, HEADS*DROPE, HEADS*DROPE, 0, HEADS*DROPE,
                         1.0f, 0, 0, 0);
        // stage2 (dependent)
        gb.d[3] = mkdesc(bf+OF_CKVH, bf+OF_CKVL, bf+OF_UKH, bf+OF_UKL, b_uk,
                         nullptr, bf+OF_KH, bf+OF_KL,
                         HEADS*SPLIT, CLAT, SPLIT, DHEAD, 0, HD, 1.0f, 0, 1, 0);
        gb.d[4] = mkdesc(bf+OF_CKVH, bf+OF_CKVL, bf+OF_UVH, nullptr, b_uv,
                         nullptr, bf+OF_VH, nullptr,
                         HD, CLAT, HD, HD, 0, HD, 1.0f, 1, 1, 0);
        gb.d[5] = mkdesc(bf+OF_CQH, bf+OF_CQL, bf+OF_UQH, bf+OF_UQL, b_uq,
                         nullptr, bf+OF_QH, bf+OF_QL,
                         HEADS*SPLIT, CLAT, SPLIT, DHEAD, 0, HD, qsc, 0, 2, 0);
        gb.d[6] = mkdesc(bf+OF_CQH, bf+OF_CQL, bf+OF_QRH, bf+OF_QRL, b_qr,
                         p_qr, nullptr, nullptr,
                         HEADS*DROPE, CLAT, HEADS*DROPE, HEADS*DROPE, 0, HEADS*DROPE,
                         1.0f, 0, 2, 0);
        finalize(gb, 7);
        int grid = gb.total < nslots ? gb.total : nslots;
        bf_gemm_ws<<<grid, 128, GSMEM>>>(gb, /*ticket*/0);
    }
    // --- rotary ---
    rotary_kernel<<<(2*NTOK*HEADS + 255)/256, 256>>>(
        p_qr, p_kr, bf+OF_QH, bf+OF_QL, bf+OF_KH, bf+OF_KL, out_krot);
    // --- attention ---
    attn_mma_kernel<<<dim3(SEQ/AM, BATCH*HEADS), 256, ASMEM>>>(
        bf+OF_QH, bf+OF_QL, bf+OF_KH, bf+OF_KL, bf+OF_VH,
        bf+OF_AOH, bf+OF_AOL);
    // --- stage 3: out-projection (2-term), own ticket ---
    {
        GBatch gb;
        gb.d[0] = mkdesc(bf+OF_AOH, bf+OF_AOL, bf+OF_OUTH, nullptr, b_out,
                         out_main, nullptr, nullptr,
                         EMB, HD, EMB, EMB, 0, EMB, 1.0f, 1, 0, 0);
        finalize(gb, 1);
        int grid = gb.total < nslots ? gb.total : nslots;
        bf_gemm_ws<<<grid, 128, GSMEM>>>(gb, /*ticket*/1);
    }
}

// round 15
// speedup vs baseline: 1.1470x; 1.0282x over previous
#include <cuda_runtime.h>
#include <cuda_fp16.h>
#include <math.h>
#include <cstdint>

// Problem constants
#define BATCH 2
#define SEQ   2048
#define EMB   2048
#define HEADS 16
#define DHEAD 128
#define DROPE 32
#define SPLIT 96
#define CLAT  512
#define NTOK  (BATCH*SEQ)          // 4096
#define HD    (HEADS*DHEAD)        // 2048

// ---------------------------------------------------------------------------
// Global scratch (fp16 planes)
// ---------------------------------------------------------------------------
constexpr size_t OF_HH   = 0;
constexpr size_t OF_HL   = OF_HH   + (size_t)NTOK*EMB;
constexpr size_t OF_DKVH = OF_HL   + (size_t)NTOK*EMB;
constexpr size_t OF_DKVL = OF_DKVH + (size_t)EMB*CLAT;
constexpr size_t OF_DQH  = OF_DKVL + (size_t)EMB*CLAT;
constexpr size_t OF_DQL  = OF_DQH  + (size_t)EMB*CLAT;
constexpr size_t OF_KRH  = OF_DQL  + (size_t)EMB*CLAT;
constexpr size_t OF_KRL  = OF_KRH  + (size_t)EMB*(HEADS*DROPE);
constexpr size_t OF_UKH  = OF_KRL  + (size_t)EMB*(HEADS*DROPE);
constexpr size_t OF_UKL  = OF_UKH  + (size_t)CLAT*(HEADS*SPLIT);
constexpr size_t OF_UVH  = OF_UKL  + (size_t)CLAT*(HEADS*SPLIT);
constexpr size_t OF_UQH  = OF_UVH  + (size_t)CLAT*HD;
constexpr size_t OF_UQL  = OF_UQH  + (size_t)CLAT*(HEADS*SPLIT);
constexpr size_t OF_QRH  = OF_UQL  + (size_t)CLAT*(HEADS*SPLIT);
constexpr size_t OF_QRL  = OF_QRH  + (size_t)CLAT*(HEADS*DROPE);
constexpr size_t OF_OUTH = OF_QRL  + (size_t)CLAT*(HEADS*DROPE);
constexpr size_t OF_CKVH = OF_OUTH + (size_t)HD*EMB;
constexpr size_t OF_CKVL = OF_CKVH + (size_t)NTOK*CLAT;
constexpr size_t OF_CQH  = OF_CKVL + (size_t)NTOK*CLAT;
constexpr size_t OF_CQL  = OF_CQH  + (size_t)NTOK*CLAT;
constexpr size_t OF_QH   = OF_CQL  + (size_t)NTOK*CLAT;
constexpr size_t OF_QL   = OF_QH   + (size_t)NTOK*HD;
constexpr size_t OF_KH   = OF_QL   + (size_t)NTOK*HD;
constexpr size_t OF_KL   = OF_KH   + (size_t)NTOK*HD;
constexpr size_t OF_VH   = OF_KL   + (size_t)NTOK*HD;
constexpr size_t OF_AOH  = OF_VH   + (size_t)NTOK*HD;
constexpr size_t OF_AOL  = OF_AOH  + (size_t)NTOK*HD;
constexpr size_t BF_TOTAL= OF_AOL  + (size_t)NTOK*HD;

__device__ __half g_bf[BF_TOTAL];
__device__ float g_qr[NTOK * HEADS * DROPE];
__device__ float g_kr[NTOK * HEADS * DROPE];
// [0]=ticket stage12, [1]=ticket stage3, [2]=ckv_done, [3]=cq_done
__device__ int   g_sync[4];

// ---------------------------------------------------------------------------
// Helpers
// ---------------------------------------------------------------------------
__device__ __forceinline__ uint32_t smem_u32(const void* p) {
    uint32_t a;
    asm("{ .reg .u64 t; cvta.to.shared.u64 t, %1; cvt.u32.u64 %0, t; }"
        : "=r"(a) : "l"(p));
    return a;
}
__device__ __forceinline__ uint32_t packhf(float e0, float e1) {
    uint32_t r;
    asm("cvt.rn.f16x2.f32 %0, %1, %2;" : "=r"(r) : "f"(e1), "f"(e0));
    return r;
}
__device__ __forceinline__ float hrt(float x) {
    return __half2float(__float2half_rn(x));
}
__device__ __forceinline__ void ldsm_x4(uint32_t& r0, uint32_t& r1, uint32_t& r2,
                                        uint32_t& r3, uint32_t addr) {
    asm volatile("ldmatrix.sync.aligned.m8n8.x4.shared.b16 {%0,%1,%2,%3}, [%4];"
                 : "=r"(r0), "=r"(r1), "=r"(r2), "=r"(r3) : "r"(addr));
}
__device__ __forceinline__ void ldsm_x4t(uint32_t& r0, uint32_t& r1, uint32_t& r2,
                                         uint32_t& r3, uint32_t addr) {
    asm volatile("ldmatrix.sync.aligned.m8n8.x4.trans.shared.b16 {%0,%1,%2,%3}, [%4];"
                 : "=r"(r0), "=r"(r1), "=r"(r2), "=r"(r3) : "r"(addr));
}
__device__ __forceinline__ void mma_f16(float* d, const uint32_t* a, const uint32_t* b) {
    asm volatile(
        "mma.sync.aligned.m16n8k16.row.col.f32.f16.f16.f32 "
        "{%0,%1,%2,%3}, {%4,%5,%6,%7}, {%8,%9}, {%0,%1,%2,%3};"
        : "+f"(d[0]), "+f"(d[1]), "+f"(d[2]), "+f"(d[3])
        : "r"(a[0]), "r"(a[1]), "r"(a[2]), "r"(a[3]), "r"(b[0]), "r"(b[1]));
}
__device__ __forceinline__ void cp16(uint32_t saddr, const void* gaddr) {
    asm volatile("cp.async.cg.shared.global [%0], [%1], 16;" :: "r"(saddr), "l"(gaddr));
}
__device__ __forceinline__ void cp_commit() {
    asm volatile("cp.async.commit_group;" ::: "memory");
}
template<int N> __device__ __forceinline__ void cp_wait() {
    asm volatile("cp.async.wait_group %0;" :: "n"(N) : "memory");
}

// ---------------------------------------------------------------------------
// Batched fp32 -> fp16 hi/lo split kernel (lo optional) + sync-counter reset
// ---------------------------------------------------------------------------
struct SDesc { const float* src; uint32_t* hi; uint32_t* lo; int end4; };
struct SBatch { SDesc d[9]; int total4; };

__global__ void split_all_kernel(SBatch sb)
{
    if (blockIdx.x == 0 && threadIdx.x < 4) g_sync[threadIdx.x] = 0;
    int i = blockIdx.x * blockDim.x + threadIdx.x;
    if (i >= sb.total4) return;
    int g = 0;
    while (i >= sb.d[g].end4) g++;
    int start = (g == 0) ? 0 : sb.d[g-1].end4;
    int li = i - start;
    float4 v = ((const float4*)sb.d[g].src)[li];
    float h0 = hrt(v.x), h1 = hrt(v.y), h2 = hrt(v.z), h3 = hrt(v.w);
    sb.d[g].hi[li*2]   = packhf(h0, h1);
    sb.d[g].hi[li*2+1] = packhf(h2, h3);
    if (sb.d[g].lo) {
        sb.d[g].lo[li*2]   = packhf(v.x - h0, v.y - h1);
        sb.d[g].lo[li*2+1] = packhf(v.z - h2, v.w - h3);
    }
}

// ---------------------------------------------------------------------------
// Persistent multi-GEMM with dynamic ticket queue + dependency counters.
// (unchanged from round 14)
// ---------------------------------------------------------------------------
#define BM 128
#define BN 128
#define BK 32
#define PA 40
#define PB 136
#define A_PLANE (BM*PA*2)
#define B_PLANE (BK*PB*2)
#define OFF_AHI 0
#define OFF_ALO (A_PLANE)
#define OFF_BHI (2*A_PLANE)
#define OFF_BLO (2*A_PLANE + B_PLANE)
#define SBUF    (2*A_PLANE + 2*B_PLANE)
#define GSMEM   (2*SBUF)
#define DEP_TARGET 128

struct GDesc {
    const __half *Ah, *Al, *Bh, *Bl;
    const float* bias;
    float* Cf;
    __half *Ch, *Cl;
    int N, K, seg, hstride, col_off, ostride;
    float scale;
    int two_term;
    int dep, sig;
    int tile_end;
};
struct GBatch { GDesc d[8]; int total; };

__device__ __forceinline__ void gemm_issue(
    const __half* Ah, const __half* Al,
    const __half* Bh, const __half* Bl, int two_term,
    int m0, int n0, int kk, int K, int N, uint32_t base, int t)
{
#pragma unroll
    for (int i = 0; i < 4; i++) {
        int f = t + i * 128;
        int m = f >> 2, g = f & 3;
        size_t gi = (size_t)(m0 + m) * K + kk + g * 8;
        uint32_t so = (uint32_t)(m * (PA*2) + g * 16);
        cp16(base + OFF_AHI + so, Ah + gi);
        cp16(base + OFF_ALO + so, Al + gi);
    }
#pragma unroll
    for (int i = 0; i < 4; i++) {
        int f = t + i * 128;
        int k2 = f >> 4, nc = f & 15;
        size_t gi = (size_t)(kk + k2) * N + n0 + nc * 8;
        uint32_t so = (uint32_t)(k2 * (PB*2) + nc * 16);
        cp16(base + OFF_BHI + so, Bh + gi);
        if (!two_term) cp16(base + OFF_BLO + so, Bl + gi);
    }
}

__global__ __launch_bounds__(128, 2)
void bf_gemm_ws(GBatch batch, int tk)
{
    extern __shared__ char smc[];
    __shared__ int s_tile;
    const uint32_t sb = smem_u32(smc);
    const int t    = threadIdx.x;
    const int lane = t & 31;
    const int w    = t >> 5;
    const int wm   = (w >> 1) * 64;
    const int wn   = (w & 1) * 64;

    const uint32_t aLane = (uint32_t)((wm + (lane & 15)) * PA + (lane >> 4) * 8) * 2;
    const uint32_t bLaneRow = (uint32_t)(lane & 15) * (PB * 2);
    const uint32_t bLaneCol = (uint32_t)(wn + (lane >> 4) * 8) * 2;

    for (;;) {
        __syncthreads();
        if (t == 0) s_tile = atomicAdd(&g_sync[tk], 1);
        __syncthreads();
        const int tile = s_tile;
        if (tile >= batch.total) break;

        int g = 0;
        while (tile >= batch.d[g].tile_end) g++;
        const GDesc& d = batch.d[g];
        const int tbase = (g == 0) ? 0 : batch.d[g-1].tile_end;
        const int lt  = tile - tbase;
        const int ntn = d.N / BN;
        const int m0  = (lt / ntn) * BM;
        const int n0  = (lt % ntn) * BN;
        const int NC  = d.K / BK;
        const int twot = d.two_term;

        if (d.dep) {
            if (t == 0) {
                while (atomicAdd(&g_sync[d.dep + 1], 0) < DEP_TARGET)
                    __nanosleep(64);
            }
            __syncthreads();
        }

        float acc[4][8][4];
#pragma unroll
        for (int i = 0; i < 4; i++)
#pragma unroll
            for (int j = 0; j < 8; j++)
#pragma unroll
                for (int r = 0; r < 4; r++) acc[i][j][r] = 0.f;

        gemm_issue(d.Ah, d.Al, d.Bh, d.Bl, twot, m0, n0, 0, d.K, d.N, sb, t);
        cp_commit();

        for (int ch = 0; ch < NC; ch++) {
            if (ch + 1 < NC) {
                gemm_issue(d.Ah, d.Al, d.Bh, d.Bl, twot, m0, n0, (ch + 1) * BK, d.K, d.N,
                           sb + (uint32_t)((ch + 1) & 1) * SBUF, t);
                cp_commit();
                cp_wait<1>();
            } else {
                cp_wait<0>();
            }
            __syncthreads();

            const uint32_t base = sb + (uint32_t)(ch & 1) * SBUF;
#pragma unroll
            for (int ks = 0; ks < 2; ks++) {
                uint32_t Fah[4][4], Fal[4][4];
                const uint32_t aOff = aLane + (uint32_t)ks * 32;
#pragma unroll
                for (int mt = 0; mt < 4; mt++) {
                    uint32_t ad = base + aOff + (uint32_t)mt * (16 * PA * 2);
                    ldsm_x4(Fah[mt][0], Fah[mt][1], Fah[mt][2], Fah[mt][3], ad + OFF_AHI);
                    ldsm_x4(Fal[mt][0], Fal[mt][1], Fal[mt][2], Fal[mt][3], ad + OFF_ALO);
                }
                const uint32_t bOff = bLaneRow + (uint32_t)ks * (16 * PB * 2) + bLaneCol;
                if (twot) {
#pragma unroll
                    for (int np = 0; np < 4; np++) {
                        uint32_t Bh[4];
                        uint32_t bd = base + bOff + (uint32_t)np * 32;
                        ldsm_x4t(Bh[0], Bh[1], Bh[2], Bh[3], bd + OFF_BHI);
#pragma unroll
                        for (int mt = 0; mt < 4; mt++) {
                            mma_f16(acc[mt][2*np],   Fah[mt], &Bh[0]);
                            mma_f16(acc[mt][2*np],   Fal[mt], &Bh[0]);
                            mma_f16(acc[mt][2*np+1], Fah[mt], &Bh[2]);
                            mma_f16(acc[mt][2*np+1], Fal[mt], &Bh[2]);
                        }
                    }
                } else {
#pragma unroll
                    for (int np = 0; np < 4; np++) {
                        uint32_t Bh[4], Bl[4];
                        uint32_t bd = base + bOff + (uint32_t)np * 32;
                        ldsm_x4t(Bh[0], Bh[1], Bh[2], Bh[3], bd + OFF_BHI);
                        ldsm_x4t(Bl[0], Bl[1], Bl[2], Bl[3], bd + OFF_BLO);
#pragma unroll
                        for (int mt = 0; mt < 4; mt++) {
                            mma_f16(acc[mt][2*np],   Fah[mt], &Bh[0]);
                            mma_f16(acc[mt][2*np],   Fah[mt], &Bl[0]);
                            mma_f16(acc[mt][2*np],   Fal[mt], &Bh[0]);
                            mma_f16(acc[mt][2*np+1], Fah[mt], &Bh[2]);
                            mma_f16(acc[mt][2*np+1], Fah[mt], &Bl[2]);
                            mma_f16(acc[mt][2*np+1], Fal[mt], &Bh[2]);
                        }
                    }
                }
            }
            __syncthreads();
        }

        const int r0 = lane >> 2;
        const int c0 = (lane & 3) * 2;
#pragma unroll
        for (int mt = 0; mt < 4; mt++) {
#pragma unroll
            for (int nt = 0; nt < 8; nt++) {
                int n = n0 + wn + nt * 8 + c0;
                int oc = (n / d.seg) * d.hstride + (n % d.seg) + d.col_off;
                float b0 = d.bias[n], b1 = d.bias[n + 1];
                int mrow0 = m0 + wm + mt * 16 + r0;
#pragma unroll
                for (int half = 0; half < 2; half++) {
                    size_t row = (size_t)(mrow0 + half * 8);
                    float v0 = (acc[mt][nt][half*2]   + b0) * d.scale;
                    float v1 = (acc[mt][nt][half*2+1] + b1) * d.scale;
                    if (d.Cf) *(float2*)&d.Cf[row * d.ostride + oc] = make_float2(v0, v1);
                    if (d.Ch) {
                        float h0 = hrt(v0), h1 = hrt(v1);
                        *(uint32_t*)&d.Ch[row * d.ostride + oc] = packhf(h0, h1);
                        if (d.Cl)
                            *(uint32_t*)&d.Cl[row * d.ostride + oc] = packhf(v0 - h0, v1 - h1);
                    }
                }
            }
        }

        __syncthreads();
        if (d.sig && t == 0) {
            __threadfence();
            atomicAdd(&g_sync[d.sig + 1], 1);
        }
    }
}

// ---------------------------------------------------------------------------
// Rotary: __sincosf + vectorized uint4 plane stores (unchanged)
// ---------------------------------------------------------------------------
__global__ void rotary_kernel(const float* __restrict__ qr,
                              const float* __restrict__ kr,
                              __half* __restrict__ qh, __half* __restrict__ ql,
                              __half* __restrict__ kh, __half* __restrict__ kl,
                              float* __restrict__ krot_out)
{
    int gid = blockIdx.x * blockDim.x + threadIdx.x;
    if (gid >= 2 * NTOK * HEADS) return;
    const bool isK = gid >= NTOK * HEADS;
    int idx = isK ? (gid - NTOK * HEADS) : gid;
    int h   = idx & (HEADS - 1);
    int tok = idx >> 4;
    int s   = tok & (SEQ - 1);
    float tpos = (float)s / 40.0f;
    const float qscale = 0.08838834764831845f;

    const float* src = isK ? kr : qr;
    float x[32];
#pragma unroll
    for (int i = 0; i < 8; i++) {
        float4 a = *(const float4*)&src[(size_t)idx * 32 + i * 4];
        x[i*4+0]=a.x; x[i*4+1]=a.y; x[i*4+2]=a.z; x[i*4+3]=a.w;
    }

    float y[32];
#pragma unroll
    for (int j = 0; j < 8; j++) {
        float invf = exp2f(-1.6609640474436813f * (float)j);
        float ang = tpos * invf;
        float sj, cj;
        __sincosf(ang, &sj, &cj);
        y[j]     = x[j] * cj - x[j + 8] * sj;
        y[j + 8] = x[j + 8] * cj + x[j] * sj;
    }
#pragma unroll
    for (int d = 16; d < 32; d++) y[d] = x[d];

    const float osc = isK ? 1.0f : qscale;
    uint32_t ph[16], pl[16];
#pragma unroll
    for (int j = 0; j < 16; j++) {
        float v0 = y[2*j] * osc, v1 = y[2*j+1] * osc;
        float h0 = hrt(v0), h1 = hrt(v1);
        ph[j] = packhf(h0, h1);
        pl[j] = packhf(v0 - h0, v1 - h1);
    }

    size_t obase = (size_t)tok * HD + h * DHEAD + SPLIT;
    __half* dsth = isK ? kh : qh;
    __half* dstl = isK ? kl : ql;
#pragma unroll
    for (int i = 0; i < 4; i++) {
        *(uint4*)&dsth[obase + 8*i] = make_uint4(ph[4*i], ph[4*i+1], ph[4*i+2], ph[4*i+3]);
        *(uint4*)&dstl[obase + 8*i] = make_uint4(pl[4*i], pl[4*i+1], pl[4*i+2], pl[4*i+3]);
    }
    if (isK) {
#pragma unroll
        for (int i = 0; i < 8; i++)
            *(float4*)&krot_out[(size_t)idx * 32 + i * 4] =
                make_float4(y[i*4], y[i*4+1], y[i*4+2], y[i*4+3]);
    }
}

// ---------------------------------------------------------------------------
// Causal flash-attention: AM=64, 128 threads (4 warps, m16 each),
// Q fragments in REGISTERS (staged once, smem reused for KV buf0),
// double-buffered 3-plane KV, 2 CTAs/SM. QK 3-term, PV 2-term.
// ---------------------------------------------------------------------------
#define AM 64
#define AN 64
#define APH 136
#define KVP  (AN*APH*2)                  // 17408 per plane
#define KVBUF (3*KVP)                    // 52224
#define ASMEM (2*KVBUF)                  // 104448 (x2 CTAs = 208896/SM)

__device__ __forceinline__ void attn_issue_kv(
    const __half* kh, const __half* kl, const __half* vh,
    size_t rowbase, uint32_t kvbase, int t)
{
#pragma unroll
    for (int i = 0; i < 8; i++) {
        int f = t + i * 128;             // 0..1023
        int row = f >> 4, ch = f & 15;
        size_t gi = (rowbase + row) * HD + ch * 8;
        uint32_t so = (uint32_t)(row * 272 + ch * 16);
        cp16(kvbase + 0*KVP + so, kh + gi);
        cp16(kvbase + 1*KVP + so, kl + gi);
        cp16(kvbase + 2*KVP + so, vh + gi);
    }
}

__global__ __launch_bounds__(128, 2)
void attn_mma_kernel(const __half* __restrict__ qh, const __half* __restrict__ ql,
                     const __half* __restrict__ kh, const __half* __restrict__ kl,
                     const __half* __restrict__ vh,
                     __half* __restrict__ aoh, __half* __restrict__ aol)
{
    extern __shared__ char smc[];
    const uint32_t sb = smem_u32(smc);
    const int t    = threadIdx.x;
    const int lane = t & 31;
    const int w    = t >> 5;
    const int bh   = blockIdx.y;
    const int b    = bh >> 4;
    const int h    = bh & 15;
    const int q0   = ((int)gridDim.x - 1 - (int)blockIdx.x) * AM;   // heavy first

    const size_t qrowbase = (size_t)(b * SEQ + q0);
    const __half* qhp = qh + h * DHEAD;
    const __half* qlp = ql + h * DHEAD;
    const __half* khp = kh + h * DHEAD;
    const __half* klp = kl + h * DHEAD;
    const __half* vhp = vh + h * DHEAD;

    // ---- stage Q hi/lo into buf0, extract fragments to registers ----
#pragma unroll
    for (int i = 0; i < 8; i++) {
        int f = t + i * 128;             // 0..1023
        int row = f >> 4, ch = f & 15;
        size_t gi = (qrowbase + row) * HD + ch * 8;
        uint32_t so = (uint32_t)(row * 272 + ch * 16);
        cp16(sb + 0   + so, qhp + gi);   // Q hi -> plane 0 of buf0
        cp16(sb + KVP + so, qlp + gi);   // Q lo -> plane 1 of buf0
    }
    cp_commit();
    cp_wait<0>();
    __syncthreads();

    uint32_t Qh[8][4], Ql[8][4];
#pragma unroll
    for (int ks = 0; ks < 8; ks++) {
        uint32_t ad = sb + (uint32_t)((w * 16 + (lane & 15)) * APH
                                      + ks * 16 + (lane >> 4) * 8) * 2;
        ldsm_x4(Qh[ks][0], Qh[ks][1], Qh[ks][2], Qh[ks][3], ad + 0);
        ldsm_x4(Ql[ks][0], Ql[ks][1], Ql[ks][2], Ql[ks][3], ad + KVP);
    }
    __syncthreads();                     // all warps done reading Q from buf0

    // ---- issue KV tile 0 into buf0 (now free) ----
    attn_issue_kv(khp, klp, vhp, (size_t)(b * SEQ), sb, t);
    cp_commit();

    float mrow[2] = {-INFINITY, -INFINITY};
    float lrow[2] = {0.f, 0.f};
    float O[16][4];
#pragma unroll
    for (int i = 0; i < 16; i++)
#pragma unroll
        for (int r = 0; r < 4; r++) O[i][r] = 0.f;

    const int ntiles = q0 / AN + 1;
    for (int nt = 0; nt < ntiles; nt++) {
        const int n0 = nt * AN;
        if (nt + 1 < ntiles) {
            attn_issue_kv(khp, klp, vhp, (size_t)(b * SEQ + (nt + 1) * AN),
                          sb + (uint32_t)((nt + 1) & 1) * KVBUF, t);
            cp_commit();
            cp_wait<1>();
        } else {
            cp_wait<0>();
        }
        __syncthreads();

        const uint32_t kvb = sb + (uint32_t)(nt & 1) * KVBUF;

        // ---- S = Q K^T (Q from registers) ----
        float S[8][4];
#pragma unroll
        for (int nf = 0; nf < 8; nf++)
#pragma unroll
            for (int r = 0; r < 4; r++) S[nf][r] = 0.f;

#pragma unroll
        for (int ks = 0; ks < 8; ks++) {
#pragma unroll
            for (int g = 0; g < 4; g++) {
                uint32_t bd = kvb + (uint32_t)((g * 16 + (lane & 7) + (lane >> 4) * 8) * APH
                                               + ks * 16 + ((lane >> 3) & 1) * 8) * 2;
                uint32_t khf[4], klf[4];
                ldsm_x4(khf[0], khf[1], khf[2], khf[3], bd + 0*KVP);
                ldsm_x4(klf[0], klf[1], klf[2], klf[3], bd + 1*KVP);
                mma_f16(S[2*g],   Qh[ks], &khf[0]);
                mma_f16(S[2*g],   Qh[ks], &klf[0]);
                mma_f16(S[2*g],   Ql[ks], &khf[0]);
                mma_f16(S[2*g+1], Qh[ks], &khf[2]);
                mma_f16(S[2*g+1], Qh[ks], &klf[2]);
                mma_f16(S[2*g+1], Ql[ks], &khf[2]);
            }
        }

        // ---- causal mask (diagonal tile only) ----
        if (n0 + AN - 1 > q0 + w * 16) {
            int grow0 = q0 + w * 16 + (lane >> 2);
#pragma unroll
            for (int nf = 0; nf < 8; nf++) {
                int col = n0 + nf * 8 + (lane & 3) * 2;
#pragma unroll
                for (int r = 0; r < 4; r++) {
                    int gr = grow0 + (r >> 1) * 8;
                    int gc = col + (r & 1);
                    if (gc > gr) S[nf][r] = -INFINITY;
                }
            }
        }

        // ---- online softmax ----
        float corr[2];
#pragma unroll
        for (int rr = 0; rr < 2; rr++) {
            float rm = -INFINITY;
#pragma unroll
            for (int nf = 0; nf < 8; nf++)
                rm = fmaxf(rm, fmaxf(S[nf][rr*2], S[nf][rr*2+1]));
            rm = fmaxf(rm, __shfl_xor_sync(0xffffffffu, rm, 1));
            rm = fmaxf(rm, __shfl_xor_sync(0xffffffffu, rm, 2));
            float mnew = fmaxf(mrow[rr], rm);
            corr[rr] = __expf(mrow[rr] - mnew);
            float rs = 0.f;
#pragma unroll
            for (int nf = 0; nf < 8; nf++) {
                float p0 = __expf(S[nf][rr*2]   - mnew);
                float p1 = __expf(S[nf][rr*2+1] - mnew);
                S[nf][rr*2]   = p0;
                S[nf][rr*2+1] = p1;
                rs += p0 + p1;
            }
            rs += __shfl_xor_sync(0xffffffffu, rs, 1);
            rs += __shfl_xor_sync(0xffffffffu, rs, 2);
            lrow[rr] = lrow[rr] * corr[rr] + rs;
            mrow[rr] = mnew;
        }
#pragma unroll
        for (int i = 0; i < 16; i++) {
            O[i][0] *= corr[0]; O[i][1] *= corr[0];
            O[i][2] *= corr[1]; O[i][3] *= corr[1];
        }

        // ---- O += P V (P hi/lo, V hi only) ----
#pragma unroll
        for (int j = 0; j < 4; j++) {
            uint32_t ph[4], pl[4];
            {
                float s00 = S[2*j][0],   s01 = S[2*j][1],   s02 = S[2*j][2],   s03 = S[2*j][3];
                float s10 = S[2*j+1][0], s11 = S[2*j+1][1], s12 = S[2*j+1][2], s13 = S[2*j+1][3];
                float h00 = hrt(s00), h01 = hrt(s01), h02 = hrt(s02), h03 = hrt(s03);
                float h10 = hrt(s10), h11 = hrt(s11), h12 = hrt(s12), h13 = hrt(s13);
                ph[0] = packhf(h00, h01); ph[1] = packhf(h02, h03);
                ph[2] = packhf(h10, h11); ph[3] = packhf(h12, h13);
                pl[0] = packhf(s00 - h00, s01 - h01); pl[1] = packhf(s02 - h02, s03 - h03);
                pl[2] = packhf(s10 - h10, s11 - h11); pl[3] = packhf(s12 - h12, s13 - h13);
            }
#pragma unroll
            for (int g = 0; g < 8; g++) {
                uint32_t vd = kvb + (uint32_t)((j * 16 + (lane & 15)) * APH
                                               + g * 16 + (lane >> 4) * 8) * 2;
                uint32_t vhf[4];
                ldsm_x4t(vhf[0], vhf[1], vhf[2], vhf[3], vd + 2*KVP);
                mma_f16(O[2*g],   ph, &vhf[0]);
                mma_f16(O[2*g],   pl, &vhf[0]);
                mma_f16(O[2*g+1], ph, &vhf[2]);
                mma_f16(O[2*g+1], pl, &vhf[2]);
            }
        }
        __syncthreads();
    }

    // ---- epilogue ----
    float inv0 = 1.0f / lrow[0];
    float inv1 = 1.0f / lrow[1];
#pragma unroll
    for (int nd = 0; nd < 16; nd++) {
        int d = nd * 8 + (lane & 3) * 2;
        size_t row0 = (size_t)(b * SEQ + q0 + w * 16 + (lane >> 2));
        float v0 = O[nd][0] * inv0, v1 = O[nd][1] * inv0;
        float h0 = hrt(v0), h1 = hrt(v1);
        *(uint32_t*)&aoh[row0 * HD + h * DHEAD + d] = packhf(h0, h1);
        *(uint32_t*)&aol[row0 * HD + h * DHEAD + d] = packhf(v0 - h0, v1 - h1);
        float v2 = O[nd][2] * inv1, v3 = O[nd][3] * inv1;
        float h2 = hrt(v2), h3 = hrt(v3);
        *(uint32_t*)&aoh[(row0 + 8) * HD + h * DHEAD + d] = packhf(h2, h3);
        *(uint32_t*)&aol[(row0 + 8) * HD + h * DHEAD + d] = packhf(v2 - h2, v3 - h3);
    }
}

// ---------------------------------------------------------------------------
// Launcher
// ---------------------------------------------------------------------------
extern "C" void kernel_launch(void* const* d_in, const int* in_sizes, int n_in,
                              void* d_out, int out_size)
{
    (void)in_sizes; (void)n_in; (void)out_size;

    const float* h_in   = (const float*)d_in[0];
    const float* W_dkv  = (const float*)d_in[1];
    const float* b_dkv  = (const float*)d_in[2];
    const float* W_dq   = (const float*)d_in[3];
    const float* b_dq   = (const float*)d_in[4];
    const float* W_uk   = (const float*)d_in[5];
    const float* b_uk   = (const float*)d_in[6];
    const float* W_uv   = (const float*)d_in[7];
    const float* b_uv   = (const float*)d_in[8];
    const float* W_uq   = (const float*)d_in[9];
    const float* b_uq   = (const float*)d_in[10];
    const float* W_qr   = (const float*)d_in[11];
    const float* b_qr   = (const float*)d_in[12];
    const float* W_kr   = (const float*)d_in[13];
    const float* b_kr   = (const float*)d_in[14];
    const float* W_out  = (const float*)d_in[15];
    const float* b_out  = (const float*)d_in[16];

    float* out_main = (float*)d_out;
    float* out_ckv  = out_main + (size_t)NTOK * EMB;
    float* out_krot = out_ckv + (size_t)NTOK * CLAT;

    __half* bf;
    float *p_qr, *p_kr;
    cudaGetSymbolAddress((void**)&bf, g_bf);
    cudaGetSymbolAddress((void**)&p_qr, g_qr);
    cudaGetSymbolAddress((void**)&p_kr, g_kr);

    int nsm = 148;
    cudaDeviceGetAttribute(&nsm, cudaDevAttrMultiProcessorCount, 0);
    const int nslots = 2 * nsm;

    cudaFuncSetAttribute(bf_gemm_ws, cudaFuncAttributeMaxDynamicSharedMemorySize, GSMEM);
    cudaFuncSetAttribute(attn_mma_kernel, cudaFuncAttributeMaxDynamicSharedMemorySize, ASMEM);

    const float qsc = 0.08838834764831845f;

    // --- one batched split launch (also zeroes g_sync) ---
    {
        SBatch sbch;
        int acc4 = 0, idx = 0;
        auto add = [&](const float* src, size_t offH, ptrdiff_t offL, size_t n) {
            acc4 += (int)(n / 4);
            sbch.d[idx].src = src;
            sbch.d[idx].hi  = (uint32_t*)(bf + offH);
            sbch.d[idx].lo  = (offL >= 0) ? (uint32_t*)(bf + offL) : nullptr;
            sbch.d[idx].end4 = acc4;
            idx++;
        };
        add(h_in,  OF_HH,   (ptrdiff_t)OF_HL,   (size_t)NTOK * EMB);
        add(W_dkv, OF_DKVH, (ptrdiff_t)OF_DKVL, (size_t)EMB * CLAT);
        add(W_dq,  OF_DQH,  (ptrdiff_t)OF_DQL,  (size_t)EMB * CLAT);
        add(W_kr,  OF_KRH,  (ptrdiff_t)OF_KRL,  (size_t)EMB * (HEADS * DROPE));
        add(W_uk,  OF_UKH,  (ptrdiff_t)OF_UKL,  (size_t)CLAT * (HEADS * SPLIT));
        add(W_uv,  OF_UVH,  (ptrdiff_t)-1,      (size_t)CLAT * HD);
        add(W_uq,  OF_UQH,  (ptrdiff_t)OF_UQL,  (size_t)CLAT * (HEADS * SPLIT));
        add(W_qr,  OF_QRH,  (ptrdiff_t)OF_QRL,  (size_t)CLAT * (HEADS * DROPE));
        add(W_out, OF_OUTH, (ptrdiff_t)-1,      (size_t)HD * EMB);
        sbch.total4 = acc4;
        split_all_kernel<<<(acc4 + 255) / 256, 256>>>(sbch);
    }

    auto mkdesc = [&](const __half* Ah, const __half* Al,
                      const __half* Bh, const __half* Bl,
                      const float* bias, float* Cf, __half* Ch, __half* Cl,
                      int N, int K, int seg, int hstride, int col_off, int ostride,
                      float scale, int two_term, int dep, int sig) {
        GDesc d;
        d.Ah = Ah; d.Al = Al; d.Bh = Bh; d.Bl = Bl;
        d.bias = bias; d.Cf = Cf; d.Ch = Ch; d.Cl = Cl;
        d.N = N; d.K = K; d.seg = seg; d.hstride = hstride;
        d.col_off = col_off; d.ostride = ostride; d.scale = scale;
        d.two_term = two_term; d.dep = dep; d.sig = sig;
        d.tile_end = 0;
        return d;
    };
    auto finalize = [&](GBatch& gb, int nd) {
        int acc = 0;
        for (int i = 0; i < 8; i++) {
            if (i < nd) { acc += (gb.d[i].N / BN) * (NTOK / BM); gb.d[i].tile_end = acc; }
            else        { gb.d[i].tile_end = 0x7fffffff; }
        }
        gb.total = acc;
    };

    // --- fused stage1+stage2 ---
    {
        GBatch gb;
        gb.d[0] = mkdesc(bf+OF_HH, bf+OF_HL, bf+OF_DKVH, bf+OF_DKVL, b_dkv,
                         out_ckv, bf+OF_CKVH, bf+OF_CKVL,
                         CLAT, EMB, CLAT, CLAT, 0, CLAT, 1.0f, 0, 0, 1);
        gb.d[1] = mkdesc(bf+OF_HH, bf+OF_HL, bf+OF_DQH, bf+OF_DQL, b_dq,
                         nullptr, bf+OF_CQH, bf+OF_CQL,
                         CLAT, EMB, CLAT, CLAT, 0, CLAT, 1.0f, 0, 0, 2);
        gb.d[2] = mkdesc(bf+OF_HH, bf+OF_HL, bf+OF_KRH, bf+OF_KRL, b_kr,
                         p_kr, nullptr, nullptr,
                         HEADS*DROPE, EMB, HEADS*DROPE, HEADS*DROPE, 0, HEADS*DROPE,
                         1.0f, 0, 0, 0);
        gb.d[3] = mkdesc(bf+OF_CKVH, bf+OF_CKVL, bf+OF_UKH, bf+OF_UKL, b_uk,
                         nullptr, bf+OF_KH, bf+OF_KL,
                         HEADS*SPLIT, CLAT, SPLIT, DHEAD, 0, HD, 1.0f, 0, 1, 0);
        gb.d[4] = mkdesc(bf+OF_CKVH, bf+OF_CKVL, bf+OF_UVH, nullptr, b_uv,
                         nullptr, bf+OF_VH, nullptr,
                         HD, CLAT, HD, HD, 0, HD, 1.0f, 1, 1, 0);
        gb.d[5] = mkdesc(bf+OF_CQH, bf+OF_CQL, bf+OF_UQH, bf+OF_UQL, b_uq,
                         nullptr, bf+OF_QH, bf+OF_QL,
                         HEADS*SPLIT, CLAT, SPLIT, DHEAD, 0, HD, qsc, 0, 2, 0);
        gb.d[6] = mkdesc(bf+OF_CQH, bf+OF_CQL, bf+OF_QRH, bf+OF_QRL, b_qr,
                         p_qr, nullptr, nullptr,
                         HEADS*DROPE, CLAT, HEADS*DROPE, HEADS*DROPE, 0, HEADS*DROPE,
                         1.0f, 0, 2, 0);
        finalize(gb, 7);
        int grid = gb.total < nslots ? gb.total : nslots;
        bf_gemm_ws<<<grid, 128, GSMEM>>>(gb, 0);
    }
    // --- rotary ---
    rotary_kernel<<<(2*NTOK*HEADS + 255)/256, 256>>>(
        p_qr, p_kr, bf+OF_QH, bf+OF_QL, bf+OF_KH, bf+OF_KL, out_krot);
    // --- attention (AM=64, 2 CTAs/SM, Q in registers) ---
    attn_mma_kernel<<<dim3(SEQ/AM, BATCH*HEADS), 128, ASMEM>>>(
        bf+OF_QH, bf+OF_QL, bf+OF_KH, bf+OF_KL, bf+OF_VH,
        bf+OF_AOH, bf+OF_AOL);
    // --- stage 3: out-projection (2-term) ---
    {
        GBatch gb;
        gb.d[0] = mkdesc(bf+OF_AOH, bf+OF_AOL, bf+OF_OUTH, nullptr, b_out,
                         out_main, nullptr, nullptr,
                         EMB, HD, EMB, EMB, 0, EMB, 1.0f, 1, 0, 0);
        finalize(gb, 1);
        int grid = gb.total < nslots ? gb.total : nslots;
        bf_gemm_ws<<<grid, 128, GSMEM>>>(gb, 1);
    }
}

// round 16
// speedup vs baseline: 1.2135x; 1.0580x over previous
#include <cuda_runtime.h>
#include <cuda_fp16.h>
#include <math.h>
#include <cstdint>

// Problem constants
#define BATCH 2
#define SEQ   2048
#define EMB   2048
#define HEADS 16
#define DHEAD 128
#define DROPE 32
#define SPLIT 96
#define CLAT  512
#define NTOK  (BATCH*SEQ)          // 4096
#define HD    (HEADS*DHEAD)        // 2048

// ---------------------------------------------------------------------------
// Global scratch (fp16 planes)
// ---------------------------------------------------------------------------
constexpr size_t OF_HH   = 0;
constexpr size_t OF_HL   = OF_HH   + (size_t)NTOK*EMB;
constexpr size_t OF_DKVH = OF_HL   + (size_t)NTOK*EMB;
constexpr size_t OF_DKVL = OF_DKVH + (size_t)EMB*CLAT;
constexpr size_t OF_DQH  = OF_DKVL + (size_t)EMB*CLAT;
constexpr size_t OF_DQL  = OF_DQH  + (size_t)EMB*CLAT;
constexpr size_t OF_KRH  = OF_DQL  + (size_t)EMB*CLAT;
constexpr size_t OF_KRL  = OF_KRH  + (size_t)EMB*(HEADS*DROPE);
constexpr size_t OF_UKH  = OF_KRL  + (size_t)EMB*(HEADS*DROPE);
constexpr size_t OF_UKL  = OF_UKH  + (size_t)CLAT*(HEADS*SPLIT);
constexpr size_t OF_UVH  = OF_UKL  + (size_t)CLAT*(HEADS*SPLIT);
constexpr size_t OF_UQH  = OF_UVH  + (size_t)CLAT*HD;
constexpr size_t OF_UQL  = OF_UQH  + (size_t)CLAT*(HEADS*SPLIT);
constexpr size_t OF_QRH  = OF_UQL  + (size_t)CLAT*(HEADS*SPLIT);
constexpr size_t OF_QRL  = OF_QRH  + (size_t)CLAT*(HEADS*DROPE);
constexpr size_t OF_OUTH = OF_QRL  + (size_t)CLAT*(HEADS*DROPE);
constexpr size_t OF_CKVH = OF_OUTH + (size_t)HD*EMB;
constexpr size_t OF_CKVL = OF_CKVH + (size_t)NTOK*CLAT;
constexpr size_t OF_CQH  = OF_CKVL + (size_t)NTOK*CLAT;
constexpr size_t OF_CQL  = OF_CQH  + (size_t)NTOK*CLAT;
constexpr size_t OF_QH   = OF_CQL  + (size_t)NTOK*CLAT;
constexpr size_t OF_QL   = OF_QH   + (size_t)NTOK*HD;
constexpr size_t OF_KH   = OF_QL   + (size_t)NTOK*HD;
constexpr size_t OF_KL   = OF_KH   + (size_t)NTOK*HD;
constexpr size_t OF_VH   = OF_KL   + (size_t)NTOK*HD;
constexpr size_t OF_AOH  = OF_VH   + (size_t)NTOK*HD;
constexpr size_t OF_AOL  = OF_AOH  + (size_t)NTOK*HD;
constexpr size_t BF_TOTAL= OF_AOL  + (size_t)NTOK*HD;

__device__ __half g_bf[BF_TOTAL];
__device__ float g_qr[NTOK * HEADS * DROPE];
__device__ float g_kr[NTOK * HEADS * DROPE];
// [0]=ticket stage12, [1]=ticket mega, [2]=ckv_done, [3]=cq_done,
// [4..36)=per-128-row-block ao completion counters (32)
__device__ int   g_sync[40];

// ---------------------------------------------------------------------------
// Helpers
// ---------------------------------------------------------------------------
__device__ __forceinline__ uint32_t smem_u32(const void* p) {
    uint32_t a;
    asm("{ .reg .u64 t; cvta.to.shared.u64 t, %1; cvt.u32.u64 %0, t; }"
        : "=r"(a) : "l"(p));
    return a;
}
__device__ __forceinline__ uint32_t packhf(float e0, float e1) {
    uint32_t r;
    asm("cvt.rn.f16x2.f32 %0, %1, %2;" : "=r"(r) : "f"(e1), "f"(e0));
    return r;
}
__device__ __forceinline__ float hrt(float x) {
    return __half2float(__float2half_rn(x));
}
__device__ __forceinline__ void ldsm_x4(uint32_t& r0, uint32_t& r1, uint32_t& r2,
                                        uint32_t& r3, uint32_t addr) {
    asm volatile("ldmatrix.sync.aligned.m8n8.x4.shared.b16 {%0,%1,%2,%3}, [%4];"
                 : "=r"(r0), "=r"(r1), "=r"(r2), "=r"(r3) : "r"(addr));
}
__device__ __forceinline__ void ldsm_x4t(uint32_t& r0, uint32_t& r1, uint32_t& r2,
                                         uint32_t& r3, uint32_t addr) {
    asm volatile("ldmatrix.sync.aligned.m8n8.x4.trans.shared.b16 {%0,%1,%2,%3}, [%4];"
                 : "=r"(r0), "=r"(r1), "=r"(r2), "=r"(r3) : "r"(addr));
}
__device__ __forceinline__ void mma_f16(float* d, const uint32_t* a, const uint32_t* b) {
    asm volatile(
        "mma.sync.aligned.m16n8k16.row.col.f32.f16.f16.f32 "
        "{%0,%1,%2,%3}, {%4,%5,%6,%7}, {%8,%9}, {%0,%1,%2,%3};"
        : "+f"(d[0]), "+f"(d[1]), "+f"(d[2]), "+f"(d[3])
        : "r"(a[0]), "r"(a[1]), "r"(a[2]), "r"(a[3]), "r"(b[0]), "r"(b[1]));
}
__device__ __forceinline__ void cp16(uint32_t saddr, const void* gaddr) {
    asm volatile("cp.async.cg.shared.global [%0], [%1], 16;" :: "r"(saddr), "l"(gaddr));
}
__device__ __forceinline__ void cp_commit() {
    asm volatile("cp.async.commit_group;" ::: "memory");
}
template<int N> __device__ __forceinline__ void cp_wait() {
    asm volatile("cp.async.wait_group %0;" :: "n"(N) : "memory");
}

// ---------------------------------------------------------------------------
// Batched fp32 -> fp16 hi/lo split kernel + sync-counter reset
// ---------------------------------------------------------------------------
struct SDesc { const float* src; uint32_t* hi; uint32_t* lo; int end4; };
struct SBatch { SDesc d[9]; int total4; };

__global__ void split_all_kernel(SBatch sb)
{
    if (blockIdx.x == 0 && threadIdx.x < 40) g_sync[threadIdx.x] = 0;
    int i = blockIdx.x * blockDim.x + threadIdx.x;
    if (i >= sb.total4) return;
    int g = 0;
    while (i >= sb.d[g].end4) g++;
    int start = (g == 0) ? 0 : sb.d[g-1].end4;
    int li = i - start;
    float4 v = ((const float4*)sb.d[g].src)[li];
    float h0 = hrt(v.x), h1 = hrt(v.y), h2 = hrt(v.z), h3 = hrt(v.w);
    sb.d[g].hi[li*2]   = packhf(h0, h1);
    sb.d[g].hi[li*2+1] = packhf(h2, h3);
    if (sb.d[g].lo) {
        sb.d[g].lo[li*2]   = packhf(v.x - h0, v.y - h1);
        sb.d[g].lo[li*2+1] = packhf(v.z - h2, v.w - h3);
    }
}

// ---------------------------------------------------------------------------
// GEMM tile worker (device function, shared by stage12 kernel and mega kernel)
// CTA 128x128, 128 threads, warp 64x64, BK=32, double-buffered cp.async.
// ---------------------------------------------------------------------------
#define BM 128
#define BN 128
#define BK 32
#define PA 40
#define PB 136
#define A_PLANE (BM*PA*2)
#define B_PLANE (BK*PB*2)
#define OFF_AHI 0
#define OFF_ALO (A_PLANE)
#define OFF_BHI (2*A_PLANE)
#define OFF_BLO (2*A_PLANE + B_PLANE)
#define SBUF    (2*A_PLANE + 2*B_PLANE)
#define GSMEM   (2*SBUF)
#define DEP_TARGET 128

struct GDesc {
    const __half *Ah, *Al, *Bh, *Bl;
    const float* bias;
    float* Cf;
    __half *Ch, *Cl;
    int N, K, seg, hstride, col_off, ostride;
    float scale;
    int two_term;
    int dep, sig;
    int tile_end;
};
struct GBatch { GDesc d[8]; int total; };

__device__ __forceinline__ void gemm_issue(
    const __half* Ah, const __half* Al,
    const __half* Bh, const __half* Bl, int two_term,
    int m0, int n0, int kk, int K, int N, uint32_t base, int t)
{
#pragma unroll
    for (int i = 0; i < 4; i++) {
        int f = t + i * 128;
        int m = f >> 2, g = f & 3;
        size_t gi = (size_t)(m0 + m) * K + kk + g * 8;
        uint32_t so = (uint32_t)(m * (PA*2) + g * 16);
        cp16(base + OFF_AHI + so, Ah + gi);
        cp16(base + OFF_ALO + so, Al + gi);
    }
#pragma unroll
    for (int i = 0; i < 4; i++) {
        int f = t + i * 128;
        int k2 = f >> 4, nc = f & 15;
        size_t gi = (size_t)(kk + k2) * N + n0 + nc * 8;
        uint32_t so = (uint32_t)(k2 * (PB*2) + nc * 16);
        cp16(base + OFF_BHI + so, Bh + gi);
        if (!two_term) cp16(base + OFF_BLO + so, Bl + gi);
    }
}

__device__ void gemm_tile(const GDesc& d, int m0, int n0, uint32_t sb, int t)
{
    const int lane = t & 31;
    const int w    = t >> 5;
    const int wm   = (w >> 1) * 64;
    const int wn   = (w & 1) * 64;
    const uint32_t aLane = (uint32_t)((wm + (lane & 15)) * PA + (lane >> 4) * 8) * 2;
    const uint32_t bLaneRow = (uint32_t)(lane & 15) * (PB * 2);
    const uint32_t bLaneCol = (uint32_t)(wn + (lane >> 4) * 8) * 2;
    const int NC  = d.K / BK;
    const int twot = d.two_term;

    float acc[4][8][4];
#pragma unroll
    for (int i = 0; i < 4; i++)
#pragma unroll
        for (int j = 0; j < 8; j++)
#pragma unroll
            for (int r = 0; r < 4; r++) acc[i][j][r] = 0.f;

    gemm_issue(d.Ah, d.Al, d.Bh, d.Bl, twot, m0, n0, 0, d.K, d.N, sb, t);
    cp_commit();

    for (int ch = 0; ch < NC; ch++) {
        if (ch + 1 < NC) {
            gemm_issue(d.Ah, d.Al, d.Bh, d.Bl, twot, m0, n0, (ch + 1) * BK, d.K, d.N,
                       sb + (uint32_t)((ch + 1) & 1) * SBUF, t);
            cp_commit();
            cp_wait<1>();
        } else {
            cp_wait<0>();
        }
        __syncthreads();

        const uint32_t base = sb + (uint32_t)(ch & 1) * SBUF;
#pragma unroll
        for (int ks = 0; ks < 2; ks++) {
            uint32_t Fah[4][4], Fal[4][4];
            const uint32_t aOff = aLane + (uint32_t)ks * 32;
#pragma unroll
            for (int mt = 0; mt < 4; mt++) {
                uint32_t ad = base + aOff + (uint32_t)mt * (16 * PA * 2);
                ldsm_x4(Fah[mt][0], Fah[mt][1], Fah[mt][2], Fah[mt][3], ad + OFF_AHI);
                ldsm_x4(Fal[mt][0], Fal[mt][1], Fal[mt][2], Fal[mt][3], ad + OFF_ALO);
            }
            const uint32_t bOff = bLaneRow + (uint32_t)ks * (16 * PB * 2) + bLaneCol;
            if (twot) {
#pragma unroll
                for (int np = 0; np < 4; np++) {
                    uint32_t Bh[4];
                    uint32_t bd = base + bOff + (uint32_t)np * 32;
                    ldsm_x4t(Bh[0], Bh[1], Bh[2], Bh[3], bd + OFF_BHI);
#pragma unroll
                    for (int mt = 0; mt < 4; mt++) {
                        mma_f16(acc[mt][2*np],   Fah[mt], &Bh[0]);
                        mma_f16(acc[mt][2*np],   Fal[mt], &Bh[0]);
                        mma_f16(acc[mt][2*np+1], Fah[mt], &Bh[2]);
                        mma_f16(acc[mt][2*np+1], Fal[mt], &Bh[2]);
                    }
                }
            } else {
#pragma unroll
                for (int np = 0; np < 4; np++) {
                    uint32_t Bh[4], Bl[4];
                    uint32_t bd = base + bOff + (uint32_t)np * 32;
                    ldsm_x4t(Bh[0], Bh[1], Bh[2], Bh[3], bd + OFF_BHI);
                    ldsm_x4t(Bl[0], Bl[1], Bl[2], Bl[3], bd + OFF_BLO);
#pragma unroll
                    for (int mt = 0; mt < 4; mt++) {
                        mma_f16(acc[mt][2*np],   Fah[mt], &Bh[0]);
                        mma_f16(acc[mt][2*np],   Fah[mt], &Bl[0]);
                        mma_f16(acc[mt][2*np],   Fal[mt], &Bh[0]);
                        mma_f16(acc[mt][2*np+1], Fah[mt], &Bh[2]);
                        mma_f16(acc[mt][2*np+1], Fah[mt], &Bl[2]);
                        mma_f16(acc[mt][2*np+1], Fal[mt], &Bh[2]);
                    }
                }
            }
        }
        __syncthreads();
    }

    const int r0 = lane >> 2;
    const int c0 = (lane & 3) * 2;
#pragma unroll
    for (int mt = 0; mt < 4; mt++) {
#pragma unroll
        for (int nt = 0; nt < 8; nt++) {
            int n = n0 + wn + nt * 8 + c0;
            int oc = (n / d.seg) * d.hstride + (n % d.seg) + d.col_off;
            float b0 = d.bias[n], b1 = d.bias[n + 1];
            int mrow0 = m0 + wm + mt * 16 + r0;
#pragma unroll
            for (int half = 0; half < 2; half++) {
                size_t row = (size_t)(mrow0 + half * 8);
                float v0 = (acc[mt][nt][half*2]   + b0) * d.scale;
                float v1 = (acc[mt][nt][half*2+1] + b1) * d.scale;
                if (d.Cf) *(float2*)&d.Cf[row * d.ostride + oc] = make_float2(v0, v1);
                if (d.Ch) {
                    float h0 = hrt(v0), h1 = hrt(v1);
                    *(uint32_t*)&d.Ch[row * d.ostride + oc] = packhf(h0, h1);
                    if (d.Cl)
                        *(uint32_t*)&d.Cl[row * d.ostride + oc] = packhf(v0 - h0, v1 - h1);
                }
            }
        }
    }
}

// ---------------------------------------------------------------------------
// Stage1+2 persistent GEMM kernel (round-14, uses gemm_tile)
// ---------------------------------------------------------------------------
__global__ __launch_bounds__(128, 2)
void bf_gemm_ws(GBatch batch, int tk)
{
    extern __shared__ char smc[];
    __shared__ int s_tile;
    const uint32_t sb = smem_u32(smc);
    const int t = threadIdx.x;

    for (;;) {
        __syncthreads();
        if (t == 0) s_tile = atomicAdd(&g_sync[tk], 1);
        __syncthreads();
        const int tile = s_tile;
        if (tile >= batch.total) break;

        int g = 0;
        while (tile >= batch.d[g].tile_end) g++;
        const GDesc& d = batch.d[g];
        const int tbase = (g == 0) ? 0 : batch.d[g-1].tile_end;
        const int lt  = tile - tbase;
        const int ntn = d.N / BN;
        const int m0  = (lt / ntn) * BM;
        const int n0  = (lt % ntn) * BN;

        if (d.dep) {
            if (t == 0) {
                while (atomicAdd(&g_sync[d.dep + 1], 0) < DEP_TARGET)
                    __nanosleep(64);
            }
            __syncthreads();
        }

        gemm_tile(d, m0, n0, sb, t);

        __syncthreads();
        if (d.sig && t == 0) {
            __threadfence();
            atomicAdd(&g_sync[d.sig + 1], 1);
        }
    }
}

// ---------------------------------------------------------------------------
// Rotary (unchanged)
// ---------------------------------------------------------------------------
__global__ void rotary_kernel(const float* __restrict__ qr,
                              const float* __restrict__ kr,
                              __half* __restrict__ qh, __half* __restrict__ ql,
                              __half* __restrict__ kh, __half* __restrict__ kl,
                              float* __restrict__ krot_out)
{
    int gid = blockIdx.x * blockDim.x + threadIdx.x;
    if (gid >= 2 * NTOK * HEADS) return;
    const bool isK = gid >= NTOK * HEADS;
    int idx = isK ? (gid - NTOK * HEADS) : gid;
    int h   = idx & (HEADS - 1);
    int tok = idx >> 4;
    int s   = tok & (SEQ - 1);
    float tpos = (float)s / 40.0f;
    const float qscale = 0.08838834764831845f;

    const float* src = isK ? kr : qr;
    float x[32];
#pragma unroll
    for (int i = 0; i < 8; i++) {
        float4 a = *(const float4*)&src[(size_t)idx * 32 + i * 4];
        x[i*4+0]=a.x; x[i*4+1]=a.y; x[i*4+2]=a.z; x[i*4+3]=a.w;
    }

    float y[32];
#pragma unroll
    for (int j = 0; j < 8; j++) {
        float invf = exp2f(-1.6609640474436813f * (float)j);
        float ang = tpos * invf;
        float sj, cj;
        __sincosf(ang, &sj, &cj);
        y[j]     = x[j] * cj - x[j + 8] * sj;
        y[j + 8] = x[j + 8] * cj + x[j] * sj;
    }
#pragma unroll
    for (int d = 16; d < 32; d++) y[d] = x[d];

    const float osc = isK ? 1.0f : qscale;
    uint32_t ph[16], pl[16];
#pragma unroll
    for (int j = 0; j < 16; j++) {
        float v0 = y[2*j] * osc, v1 = y[2*j+1] * osc;
        float h0 = hrt(v0), h1 = hrt(v1);
        ph[j] = packhf(h0, h1);
        pl[j] = packhf(v0 - h0, v1 - h1);
    }

    size_t obase = (size_t)tok * HD + h * DHEAD + SPLIT;
    __half* dsth = isK ? kh : qh;
    __half* dstl = isK ? kl : ql;
#pragma unroll
    for (int i = 0; i < 4; i++) {
        *(uint4*)&dsth[obase + 8*i] = make_uint4(ph[4*i], ph[4*i+1], ph[4*i+2], ph[4*i+3]);
        *(uint4*)&dstl[obase + 8*i] = make_uint4(pl[4*i], pl[4*i+1], pl[4*i+2], pl[4*i+3]);
    }
    if (isK) {
#pragma unroll
        for (int i = 0; i < 8; i++)
            *(float4*)&krot_out[(size_t)idx * 32 + i * 4] =
                make_float4(y[i*4], y[i*4+1], y[i*4+2], y[i*4+3]);
    }
}

// ---------------------------------------------------------------------------
// MEGA kernel: attention tiles (tickets 0..1023) then out-proj tiles
// (1024..1535) with per-row-block dependency counters.
// Attention: AM=64, 128 thr, Q in regs, double-buffered 3-plane KV.
// ---------------------------------------------------------------------------
#define AM 64
#define AN 64
#define APH 136
#define KVP  (AN*APH*2)
#define KVBUF (3*KVP)
#define ASMEM (2*KVBUF)                  // 104448
#define AT_TILES 1024                    // 32 q-levels x 32 (b,h)
#define S3_TILES 512                     // 32 m-blocks x 16 n-tiles
#define BLK_DEP 32                       // 16 heads x 2 q-halves per 128-row block

__device__ __forceinline__ void attn_issue_kv(
    const __half* kh, const __half* kl, const __half* vh,
    size_t rowbase, uint32_t kvbase, int t)
{
#pragma unroll
    for (int i = 0; i < 8; i++) {
        int f = t + i * 128;
        int row = f >> 4, ch = f & 15;
        size_t gi = (rowbase + row) * HD + ch * 8;
        uint32_t so = (uint32_t)(row * 272 + ch * 16);
        cp16(kvbase + 0*KVP + so, kh + gi);
        cp16(kvbase + 1*KVP + so, kl + gi);
        cp16(kvbase + 2*KVP + so, vh + gi);
    }
}

__global__ __launch_bounds__(128, 2)
void mega_kernel(const __half* __restrict__ qh, const __half* __restrict__ ql,
                 const __half* __restrict__ kh, const __half* __restrict__ kl,
                 const __half* __restrict__ vh,
                 __half* __restrict__ aoh, __half* __restrict__ aol,
                 GDesc outd)
{
    extern __shared__ char smc[];
    __shared__ int s_tile;
    const uint32_t sb = smem_u32(smc);
    const int t    = threadIdx.x;
    const int lane = t & 31;
    const int w    = t >> 5;

    for (;;) {
        __syncthreads();
        if (t == 0) s_tile = atomicAdd(&g_sync[1], 1);
        __syncthreads();
        const int tile = s_tile;
        if (tile >= AT_TILES + S3_TILES) break;

        if (tile < AT_TILES) {
            // ================= attention tile =================
            const int qi = tile >> 5;                  // 0..31, heavy first
            const int bh = tile & 31;
            const int b  = bh >> 4;
            const int h  = bh & 15;
            const int q0 = (31 - qi) * AM;

            const size_t qrowbase = (size_t)(b * SEQ + q0);
            const __half* qhp = qh + h * DHEAD;
            const __half* qlp = ql + h * DHEAD;
            const __half* khp = kh + h * DHEAD;
            const __half* klp = kl + h * DHEAD;
            const __half* vhp = vh + h * DHEAD;

            // stage Q into buf0, extract to registers
#pragma unroll
            for (int i = 0; i < 8; i++) {
                int f = t + i * 128;
                int row = f >> 4, ch = f & 15;
                size_t gi = (qrowbase + row) * HD + ch * 8;
                uint32_t so = (uint32_t)(row * 272 + ch * 16);
                cp16(sb + 0   + so, qhp + gi);
                cp16(sb + KVP + so, qlp + gi);
            }
            cp_commit();
            cp_wait<0>();
            __syncthreads();

            uint32_t Qh[8][4], Ql[8][4];
#pragma unroll
            for (int ks = 0; ks < 8; ks++) {
                uint32_t ad = sb + (uint32_t)((w * 16 + (lane & 15)) * APH
                                              + ks * 16 + (lane >> 4) * 8) * 2;
                ldsm_x4(Qh[ks][0], Qh[ks][1], Qh[ks][2], Qh[ks][3], ad + 0);
                ldsm_x4(Ql[ks][0], Ql[ks][1], Ql[ks][2], Ql[ks][3], ad + KVP);
            }
            __syncthreads();

            attn_issue_kv(khp, klp, vhp, (size_t)(b * SEQ), sb, t);
            cp_commit();

            float mrow[2] = {-INFINITY, -INFINITY};
            float lrow[2] = {0.f, 0.f};
            float O[16][4];
#pragma unroll
            for (int i = 0; i < 16; i++)
#pragma unroll
                for (int r = 0; r < 4; r++) O[i][r] = 0.f;

            const int ntiles = q0 / AN + 1;
            for (int nt = 0; nt < ntiles; nt++) {
                const int n0 = nt * AN;
                if (nt + 1 < ntiles) {
                    attn_issue_kv(khp, klp, vhp, (size_t)(b * SEQ + (nt + 1) * AN),
                                  sb + (uint32_t)((nt + 1) & 1) * KVBUF, t);
                    cp_commit();
                    cp_wait<1>();
                } else {
                    cp_wait<0>();
                }
                __syncthreads();

                const uint32_t kvb = sb + (uint32_t)(nt & 1) * KVBUF;

                float S[8][4];
#pragma unroll
                for (int nf = 0; nf < 8; nf++)
#pragma unroll
                    for (int r = 0; r < 4; r++) S[nf][r] = 0.f;

#pragma unroll
                for (int ks = 0; ks < 8; ks++) {
#pragma unroll
                    for (int g = 0; g < 4; g++) {
                        uint32_t bd = kvb + (uint32_t)((g * 16 + (lane & 7) + (lane >> 4) * 8) * APH
                                                       + ks * 16 + ((lane >> 3) & 1) * 8) * 2;
                        uint32_t khf[4], klf[4];
                        ldsm_x4(khf[0], khf[1], khf[2], khf[3], bd + 0*KVP);
                        ldsm_x4(klf[0], klf[1], klf[2], klf[3], bd + 1*KVP);
                        mma_f16(S[2*g],   Qh[ks], &khf[0]);
                        mma_f16(S[2*g],   Qh[ks], &klf[0]);
                        mma_f16(S[2*g],   Ql[ks], &khf[0]);
                        mma_f16(S[2*g+1], Qh[ks], &khf[2]);
                        mma_f16(S[2*g+1], Qh[ks], &klf[2]);
                        mma_f16(S[2*g+1], Ql[ks], &khf[2]);
                    }
                }

                if (n0 + AN - 1 > q0 + w * 16) {
                    int grow0 = q0 + w * 16 + (lane >> 2);
#pragma unroll
                    for (int nf = 0; nf < 8; nf++) {
                        int col = n0 + nf * 8 + (lane & 3) * 2;
#pragma unroll
                        for (int r = 0; r < 4; r++) {
                            int gr = grow0 + (r >> 1) * 8;
                            int gc = col + (r & 1);
                            if (gc > gr) S[nf][r] = -INFINITY;
                        }
                    }
                }

                float corr[2];
#pragma unroll
                for (int rr = 0; rr < 2; rr++) {
                    float rm = -INFINITY;
#pragma unroll
                    for (int nf = 0; nf < 8; nf++)
                        rm = fmaxf(rm, fmaxf(S[nf][rr*2], S[nf][rr*2+1]));
                    rm = fmaxf(rm, __shfl_xor_sync(0xffffffffu, rm, 1));
                    rm = fmaxf(rm, __shfl_xor_sync(0xffffffffu, rm, 2));
                    float mnew = fmaxf(mrow[rr], rm);
                    corr[rr] = __expf(mrow[rr] - mnew);
                    float rs = 0.f;
#pragma unroll
                    for (int nf = 0; nf < 8; nf++) {
                        float p0 = __expf(S[nf][rr*2]   - mnew);
                        float p1 = __expf(S[nf][rr*2+1] - mnew);
                        S[nf][rr*2]   = p0;
                        S[nf][rr*2+1] = p1;
                        rs += p0 + p1;
                    }
                    rs += __shfl_xor_sync(0xffffffffu, rs, 1);
                    rs += __shfl_xor_sync(0xffffffffu, rs, 2);
                    lrow[rr] = lrow[rr] * corr[rr] + rs;
                    mrow[rr] = mnew;
                }
#pragma unroll
                for (int i = 0; i < 16; i++) {
                    O[i][0] *= corr[0]; O[i][1] *= corr[0];
                    O[i][2] *= corr[1]; O[i][3] *= corr[1];
                }

#pragma unroll
                for (int j = 0; j < 4; j++) {
                    uint32_t ph[4], pl[4];
                    {
                        float s00 = S[2*j][0],   s01 = S[2*j][1],   s02 = S[2*j][2],   s03 = S[2*j][3];
                        float s10 = S[2*j+1][0], s11 = S[2*j+1][1], s12 = S[2*j+1][2], s13 = S[2*j+1][3];
                        float h00 = hrt(s00), h01 = hrt(s01), h02 = hrt(s02), h03 = hrt(s03);
                        float h10 = hrt(s10), h11 = hrt(s11), h12 = hrt(s12), h13 = hrt(s13);
                        ph[0] = packhf(h00, h01); ph[1] = packhf(h02, h03);
                        ph[2] = packhf(h10, h11); ph[3] = packhf(h12, h13);
                        pl[0] = packhf(s00 - h00, s01 - h01); pl[1] = packhf(s02 - h02, s03 - h03);
                        pl[2] = packhf(s10 - h10, s11 - h11); pl[3] = packhf(s12 - h12, s13 - h13);
                    }
#pragma unroll
                    for (int g = 0; g < 8; g++) {
                        uint32_t vd = kvb + (uint32_t)((j * 16 + (lane & 15)) * APH
                                                       + g * 16 + (lane >> 4) * 8) * 2;
                        uint32_t vhf[4];
                        ldsm_x4t(vhf[0], vhf[1], vhf[2], vhf[3], vd + 2*KVP);
                        mma_f16(O[2*g],   ph, &vhf[0]);
                        mma_f16(O[2*g],   pl, &vhf[0]);
                        mma_f16(O[2*g+1], ph, &vhf[2]);
                        mma_f16(O[2*g+1], pl, &vhf[2]);
                    }
                }
                __syncthreads();
            }

            float inv0 = 1.0f / lrow[0];
            float inv1 = 1.0f / lrow[1];
#pragma unroll
            for (int nd = 0; nd < 16; nd++) {
                int d = nd * 8 + (lane & 3) * 2;
                size_t row0 = (size_t)(b * SEQ + q0 + w * 16 + (lane >> 2));
                float v0 = O[nd][0] * inv0, v1 = O[nd][1] * inv0;
                float h0 = hrt(v0), h1 = hrt(v1);
                *(uint32_t*)&aoh[row0 * HD + h * DHEAD + d] = packhf(h0, h1);
                *(uint32_t*)&aol[row0 * HD + h * DHEAD + d] = packhf(v0 - h0, v1 - h1);
                float v2 = O[nd][2] * inv1, v3 = O[nd][3] * inv1;
                float h2 = hrt(v2), h3 = hrt(v3);
                *(uint32_t*)&aoh[(row0 + 8) * HD + h * DHEAD + d] = packhf(h2, h3);
                *(uint32_t*)&aol[(row0 + 8) * HD + h * DHEAD + d] = packhf(v2 - h2, v3 - h3);
            }

            // signal row-block completion
            __syncthreads();
            if (t == 0) {
                __threadfence();
                int blk = (int)(((size_t)(b * SEQ + q0)) >> 7);
                atomicAdd(&g_sync[4 + blk], 1);
            }
        } else {
            // ================= out-projection tile =================
            const int st = tile - AT_TILES;
            const int mb = 31 - (st >> 4);          // m-blocks descending
            const int m0 = mb * BM;
            const int n0 = (st & 15) * BN;

            if (t == 0) {
                while (atomicAdd(&g_sync[4 + mb], 0) < BLK_DEP)
                    __nanosleep(64);
            }
            __syncthreads();

            gemm_tile(outd, m0, n0, sb, t);
        }
    }
}

// ---------------------------------------------------------------------------
// Launcher
// ---------------------------------------------------------------------------
extern "C" void kernel_launch(void* const* d_in, const int* in_sizes, int n_in,
                              void* d_out, int out_size)
{
    (void)in_sizes; (void)n_in; (void)out_size;

    const float* h_in   = (const float*)d_in[0];
    const float* W_dkv  = (const float*)d_in[1];
    const float* b_dkv  = (const float*)d_in[2];
    const float* W_dq   = (const float*)d_in[3];
    const float* b_dq   = (const float*)d_in[4];
    const float* W_uk   = (const float*)d_in[5];
    const float* b_uk   = (const float*)d_in[6];
    const float* W_uv   = (const float*)d_in[7];
    const float* b_uv   = (const float*)d_in[8];
    const float* W_uq   = (const float*)d_in[9];
    const float* b_uq   = (const float*)d_in[10];
    const float* W_qr   = (const float*)d_in[11];
    const float* b_qr   = (const float*)d_in[12];
    const float* W_kr   = (const float*)d_in[13];
    const float* b_kr   = (const float*)d_in[14];
    const float* W_out  = (const float*)d_in[15];
    const float* b_out  = (const float*)d_in[16];

    float* out_main = (float*)d_out;
    float* out_ckv  = out_main + (size_t)NTOK * EMB;
    float* out_krot = out_ckv + (size_t)NTOK * CLAT;

    __half* bf;
    float *p_qr, *p_kr;
    cudaGetSymbolAddress((void**)&bf, g_bf);
    cudaGetSymbolAddress((void**)&p_qr, g_qr);
    cudaGetSymbolAddress((void**)&p_kr, g_kr);

    int nsm = 148;
    cudaDeviceGetAttribute(&nsm, cudaDevAttrMultiProcessorCount, 0);
    const int nslots = 2 * nsm;

    cudaFuncSetAttribute(bf_gemm_ws, cudaFuncAttributeMaxDynamicSharedMemorySize, GSMEM);
    cudaFuncSetAttribute(mega_kernel, cudaFuncAttributeMaxDynamicSharedMemorySize, ASMEM);

    const float qsc = 0.08838834764831845f;

    // --- one batched split launch (also zeroes g_sync) ---
    {
        SBatch sbch;
        int acc4 = 0, idx = 0;
        auto add = [&](const float* src, size_t offH, ptrdiff_t offL, size_t n) {
            acc4 += (int)(n / 4);
            sbch.d[idx].src = src;
            sbch.d[idx].hi  = (uint32_t*)(bf + offH);
            sbch.d[idx].lo  = (offL >= 0) ? (uint32_t*)(bf + offL) : nullptr;
            sbch.d[idx].end4 = acc4;
            idx++;
        };
        add(h_in,  OF_HH,   (ptrdiff_t)OF_HL,   (size_t)NTOK * EMB);
        add(W_dkv, OF_DKVH, (ptrdiff_t)OF_DKVL, (size_t)EMB * CLAT);
        add(W_dq,  OF_DQH,  (ptrdiff_t)OF_DQL,  (size_t)EMB * CLAT);
        add(W_kr,  OF_KRH,  (ptrdiff_t)OF_KRL,  (size_t)EMB * (HEADS * DROPE));
        add(W_uk,  OF_UKH,  (ptrdiff_t)OF_UKL,  (size_t)CLAT * (HEADS * SPLIT));
        add(W_uv,  OF_UVH,  (ptrdiff_t)-1,      (size_t)CLAT * HD);
        add(W_uq,  OF_UQH,  (ptrdiff_t)OF_UQL,  (size_t)CLAT * (HEADS * SPLIT));
        add(W_qr,  OF_QRH,  (ptrdiff_t)OF_QRL,  (size_t)CLAT * (HEADS * DROPE));
        add(W_out, OF_OUTH, (ptrdiff_t)-1,      (size_t)HD * EMB);
        sbch.total4 = acc4;
        split_all_kernel<<<(acc4 + 255) / 256, 256>>>(sbch);
    }

    auto mkdesc = [&](const __half* Ah, const __half* Al,
                      const __half* Bh, const __half* Bl,
                      const float* bias, float* Cf, __half* Ch, __half* Cl,
                      int N, int K, int seg, int hstride, int col_off, int ostride,
                      float scale, int two_term, int dep, int sig) {
        GDesc d;
        d.Ah = Ah; d.Al = Al; d.Bh = Bh; d.Bl = Bl;
        d.bias = bias; d.Cf = Cf; d.Ch = Ch; d.Cl = Cl;
        d.N = N; d.K = K; d.seg = seg; d.hstride = hstride;
        d.col_off = col_off; d.ostride = ostride; d.scale = scale;
        d.two_term = two_term; d.dep = dep; d.sig = sig;
        d.tile_end = 0;
        return d;
    };
    auto finalize = [&](GBatch& gb, int nd) {
        int acc = 0;
        for (int i = 0; i < 8; i++) {
            if (i < nd) { acc += (gb.d[i].N / BN) * (NTOK / BM); gb.d[i].tile_end = acc; }
            else        { gb.d[i].tile_end = 0x7fffffff; }
        }
        gb.total = acc;
    };

    // --- fused stage1+stage2 ---
    {
        GBatch gb;
        gb.d[0] = mkdesc(bf+OF_HH, bf+OF_HL, bf+OF_DKVH, bf+OF_DKVL, b_dkv,
                         out_ckv, bf+OF_CKVH, bf+OF_CKVL,
                         CLAT, EMB, CLAT, CLAT, 0, CLAT, 1.0f, 0, 0, 1);
        gb.d[1] = mkdesc(bf+OF_HH, bf+OF_HL, bf+OF_DQH, bf+OF_DQL, b_dq,
                         nullptr, bf+OF_CQH, bf+OF_CQL,
                         CLAT, EMB, CLAT, CLAT, 0, CLAT, 1.0f, 0, 0, 2);
        gb.d[2] = mkdesc(bf+OF_HH, bf+OF_HL, bf+OF_KRH, bf+OF_KRL, b_kr,
                         p_kr, nullptr, nullptr,
                         HEADS*DROPE, EMB, HEADS*DROPE, HEADS*DROPE, 0, HEADS*DROPE,
                         1.0f, 0, 0, 0);
        gb.d[3] = mkdesc(bf+OF_CKVH, bf+OF_CKVL, bf+OF_UKH, bf+OF_UKL, b_uk,
                         nullptr, bf+OF_KH, bf+OF_KL,
                         HEADS*SPLIT, CLAT, SPLIT, DHEAD, 0, HD, 1.0f, 0, 1, 0);
        gb.d[4] = mkdesc(bf+OF_CKVH, bf+OF_CKVL, bf+OF_UVH, nullptr, b_uv,
                         nullptr, bf+OF_VH, nullptr,
                         HD, CLAT, HD, HD, 0, HD, 1.0f, 1, 1, 0);
        gb.d[5] = mkdesc(bf+OF_CQH, bf+OF_CQL, bf+OF_UQH, bf+OF_UQL, b_uq,
                         nullptr, bf+OF_QH, bf+OF_QL,
                         HEADS*SPLIT, CLAT, SPLIT, DHEAD, 0, HD, qsc, 0, 2, 0);
        gb.d[6] = mkdesc(bf+OF_CQH, bf+OF_CQL, bf+OF_QRH, bf+OF_QRL, b_qr,
                         p_qr, nullptr, nullptr,
                         HEADS*DROPE, CLAT, HEADS*DROPE, HEADS*DROPE, 0, HEADS*DROPE,
                         1.0f, 0, 2, 0);
        finalize(gb, 7);
        int grid = gb.total < nslots ? gb.total : nslots;
        bf_gemm_ws<<<grid, 128, GSMEM>>>(gb, 0);
    }
    // --- rotary ---
    rotary_kernel<<<(2*NTOK*HEADS + 255)/256, 256>>>(
        p_qr, p_kr, bf+OF_QH, bf+OF_QL, bf+OF_KH, bf+OF_KL, out_krot);
    // --- MEGA: attention + out-projection overlapped ---
    {
        GDesc outd = mkdesc(bf+OF_AOH, bf+OF_AOL, bf+OF_OUTH, nullptr, b_out,
                            out_main, nullptr, nullptr,
                            EMB, HD, EMB, EMB, 0, EMB, 1.0f, 1, 0, 0);
        int total = AT_TILES + S3_TILES;
        int grid = total < nslots ? total : nslots;
        mega_kernel<<<grid, 128, ASMEM>>>(
            bf+OF_QH, bf+OF_QL, bf+OF_KH, bf+OF_KL, bf+OF_VH,
            bf+OF_AOH, bf+OF_AOL, outd);
    }
}